// round 3
// baseline (speedup 1.0000x reference)
#include <cuda_runtime.h>
#include <cuda_bf16.h>
#include <math.h>

// ---------------- problem constants ----------------
#define BATCH   8
#define GH      40
#define GW      40
#define MPIL    (BATCH*GH*GW)      // 12800 pillars
#define NPTS    32
#define CIN     6
#define CF      256
#define NFEAT   12                 // CIN + 6

#define M1      800                // 8 batches * 10*10 needed conv1 pixels
#define N1      1024
#define K1      2304               // 9 taps * 256
#define M2      800
#define N2      4096
#define K2      1024

#define OUT_MAIN (M2*N2)           // 3276800

// ---------------- device scratch (no dynamic alloc allowed) ----------------
__device__ float g_canvas[BATCH*GH*GW*CF];   // NHWC  (b, y, x, c)
__device__ float g_w1t[K1*N1];               // [k = tap*256+ci][o]
__device__ float g_w2t[K2*N2];               // [k][o]
__device__ float g_c1out[M1*N1];             // relu(conv1+b) at even pixels, [m][o]
__device__ int   g_valid[M2];

// ---------------- weight transposes ----------------
__global__ void transpose_w1_kernel(const float* __restrict__ w) {
    int idx = blockIdx.x * blockDim.x + threadIdx.x;   // k*1024 + o
    if (idx >= K1*N1) return;
    int o  = idx & (N1-1);
    int k  = idx >> 10;
    int tap = k >> 8;          // 0..8
    int ci  = k & 255;
    g_w1t[idx] = w[(size_t)(o*CF + ci)*9 + tap];
}

__global__ void transpose_w2_kernel(const float* __restrict__ w) {
    int idx = blockIdx.x * blockDim.x + threadIdx.x;   // k*4096 + o
    if (idx >= K2*N2) return;
    int o = idx & (N2-1);
    int k = idx >> 12;
    g_w2t[idx] = w[(size_t)o*K2 + k];
}

// ---------------- PFN: per-pillar feature net ----------------
__global__ __launch_bounds__(CF) void pfn_kernel(
    const float* __restrict__ voxels,     // (M,32,6)
    const int*   __restrict__ num_points, // (M,)
    const int*   __restrict__ coors,      // (M,4)
    const float* __restrict__ w,          // (12,256)
    const float* __restrict__ bn_gamma,
    const float* __restrict__ bn_beta,
    const float* __restrict__ bn_mean,
    const float* __restrict__ bn_var)
{
    int m = blockIdx.x;
    int f = threadIdx.x;                     // output channel
    __shared__ float feats[NPTS][NFEAT];
    __shared__ float smean[3];

    int np = num_points[m];
    const float* vox = voxels + (size_t)m * NPTS * CIN;

    float x=0.f, y=0.f, z=0.f, msk=0.f;
    if (f < NPTS) {
        int n = f;
        msk = (n < np) ? 1.0f : 0.0f;
        x = vox[n*CIN+0];  y = vox[n*CIN+1];  z = vox[n*CIN+2];
        float mx = x*msk, my = y*msk, mz = z*msk;
        #pragma unroll
        for (int o = 16; o; o >>= 1) {
            mx += __shfl_xor_sync(0xffffffffu, mx, o);
            my += __shfl_xor_sync(0xffffffffu, my, o);
            mz += __shfl_xor_sync(0xffffffffu, mz, o);
        }
        if (n == 0) {
            float inv = 1.0f / (float)np;    // np >= 1
            smean[0] = mx*inv; smean[1] = my*inv; smean[2] = mz*inv;
        }
    }
    __syncthreads();

    if (f < NPTS) {
        int n = f;
        float cx = (float)coors[m*4+3] * 0.025f + (0.0125f - 0.5f);
        float cy = (float)coors[m*4+2] * 0.025f + (0.0125f - 0.5f);
        float cz = (float)coors[m*4+1] * 1.0f   + 0.5f;
        feats[n][0]  = x*msk;
        feats[n][1]  = y*msk;
        feats[n][2]  = z*msk;
        feats[n][3]  = vox[n*CIN+3]*msk;
        feats[n][4]  = vox[n*CIN+4]*msk;
        feats[n][5]  = vox[n*CIN+5]*msk;
        feats[n][6]  = (x - smean[0])*msk;
        feats[n][7]  = (y - smean[1])*msk;
        feats[n][8]  = (z - smean[2])*msk;
        feats[n][9]  = (x - cx)*msk;
        feats[n][10] = (y - cy)*msk;
        feats[n][11] = (z - cz)*msk;
    }
    __syncthreads();

    float wreg[NFEAT];
    #pragma unroll
    for (int d = 0; d < NFEAT; d++) wreg[d] = w[d*CF + f];
    float scale = bn_gamma[f] * rsqrtf(bn_var[f] + 1e-3f);
    float bm = bn_mean[f], bb = bn_beta[f];

    float vmax = 0.0f;  // relu output >= 0
    #pragma unroll
    for (int n = 0; n < NPTS; n++) {
        float s = 0.0f;
        #pragma unroll
        for (int d = 0; d < NFEAT; d++) s = fmaf(feats[n][d], wreg[d], s);
        float h = (s - bm) * scale + bb;
        h = fmaxf(h, 0.0f);
        vmax = fmaxf(vmax, h);
    }

    int b  = coors[m*4+0];
    int yy = coors[m*4+2];
    int xx = coors[m*4+3];
    g_canvas[(((size_t)b*GH + yy)*GW + xx)*CF + f] = vmax;
}

// ---------------- conv1 implicit GEMM (only even output pixels) ----------------
// C[m][o] = relu( sum_k A[m][k] * w1t[k][o] + b1[o] )
// m = b*100 + hp*10 + wp ; conv1 output pixel (2hp, 2wp); ih = 4hp + kh - 1
__global__ __launch_bounds__(256) void conv1_gemm_kernel(const float* __restrict__ bias) {
    __shared__ float As[16][68];     // k-major, padded
    __shared__ float Bs[16][64];

    int tid = threadIdx.x;
    int bn = blockIdx.x * 64;
    int bm = blockIdx.y * 64;
    int tx = tid & 15, ty = tid >> 4;

    int a_m = tid >> 2;
    int a_k = (tid & 3) << 2;
    int gm  = bm + a_m;
    bool mok = gm < M1;
    int gmc = mok ? gm : 0;
    int b  = gmc / 100;
    int p  = gmc - b*100;
    int hp = p / 10, wp = p - hp*10;
    int ihb = 4*hp - 1, iwb = 4*wp - 1;
    const float* cbase = g_canvas + (size_t)b * (GH*GW*CF);

    int b_k = tid >> 6;      // 0..3
    int b_n = tid & 63;

    float acc[4][4];
    #pragma unroll
    for (int i=0;i<4;i++)
        #pragma unroll
        for (int j=0;j<4;j++) acc[i][j]=0.f;

    for (int k0 = 0; k0 < K1; k0 += 16) {
        int tap = k0 >> 8;
        int ci0 = k0 & 255;
        int kh = tap / 3, kw = tap - 3*kh;
        int ih = ihb + kh, iw = iwb + kw;
        float4 av = make_float4(0.f,0.f,0.f,0.f);
        if (mok && (unsigned)ih < (unsigned)GH && (unsigned)iw < (unsigned)GW)
            av = *(const float4*)(cbase + ((size_t)(ih*GW + iw))*CF + ci0 + a_k);
        As[a_k+0][a_m] = av.x;
        As[a_k+1][a_m] = av.y;
        As[a_k+2][a_m] = av.z;
        As[a_k+3][a_m] = av.w;
        #pragma unroll
        for (int r = 0; r < 4; r++)
            Bs[b_k + 4*r][b_n] = g_w1t[(size_t)(k0 + b_k + 4*r)*N1 + bn + b_n];
        __syncthreads();
        #pragma unroll
        for (int kk = 0; kk < 16; kk++) {
            float4 a4 = *(const float4*)&As[kk][ty<<2];
            float4 b4 = *(const float4*)&Bs[kk][tx<<2];
            float av_[4] = {a4.x, a4.y, a4.z, a4.w};
            float bv_[4] = {b4.x, b4.y, b4.z, b4.w};
            #pragma unroll
            for (int i=0;i<4;i++)
                #pragma unroll
                for (int j=0;j<4;j++) acc[i][j] = fmaf(av_[i], bv_[j], acc[i][j]);
        }
        __syncthreads();
    }

    int cn = bn + (tx<<2);
    float4 b4 = *(const float4*)(bias + cn);
    #pragma unroll
    for (int i=0;i<4;i++) {
        int m = bm + (ty<<2) + i;
        if (m < M1) {
            float4 r;
            r.x = fmaxf(acc[i][0] + b4.x, 0.f);
            r.y = fmaxf(acc[i][1] + b4.y, 0.f);
            r.z = fmaxf(acc[i][2] + b4.z, 0.f);
            r.w = fmaxf(acc[i][3] + b4.w, 0.f);
            *(float4*)(g_c1out + (size_t)m*N1 + cn) = r;
        }
    }
}

// ---------------- conv2 GEMM (1x1, writes straight to d_out) ----------------
__global__ __launch_bounds__(256) void conv2_gemm_kernel(const float* __restrict__ bias,
                                                         float* __restrict__ out) {
    __shared__ float As[16][68];
    __shared__ float Bs[16][64];

    int tid = threadIdx.x;
    int bn = blockIdx.x * 64;
    int bm = blockIdx.y * 64;
    int tx = tid & 15, ty = tid >> 4;

    int a_m = tid >> 2;
    int a_k = (tid & 3) << 2;
    int gm  = bm + a_m;
    bool mok = gm < M2;

    int b_k = tid >> 6;
    int b_n = tid & 63;

    float acc[4][4];
    #pragma unroll
    for (int i=0;i<4;i++)
        #pragma unroll
        for (int j=0;j<4;j++) acc[i][j]=0.f;

    for (int k0 = 0; k0 < K2; k0 += 16) {
        float4 av = make_float4(0.f,0.f,0.f,0.f);
        if (mok)
            av = *(const float4*)(g_c1out + (size_t)gm*K2 + k0 + a_k);
        As[a_k+0][a_m] = av.x;
        As[a_k+1][a_m] = av.y;
        As[a_k+2][a_m] = av.z;
        As[a_k+3][a_m] = av.w;
        #pragma unroll
        for (int r = 0; r < 4; r++)
            Bs[b_k + 4*r][b_n] = g_w2t[(size_t)(k0 + b_k + 4*r)*N2 + bn + b_n];
        __syncthreads();
        #pragma unroll
        for (int kk = 0; kk < 16; kk++) {
            float4 a4 = *(const float4*)&As[kk][ty<<2];
            float4 b4 = *(const float4*)&Bs[kk][tx<<2];
            float av_[4] = {a4.x, a4.y, a4.z, a4.w};
            float bv_[4] = {b4.x, b4.y, b4.z, b4.w};
            #pragma unroll
            for (int i=0;i<4;i++)
                #pragma unroll
                for (int j=0;j<4;j++) acc[i][j] = fmaf(av_[i], bv_[j], acc[i][j]);
        }
        __syncthreads();
    }

    int cn = bn + (tx<<2);
    float4 b4 = *(const float4*)(bias + cn);
    #pragma unroll
    for (int i=0;i<4;i++) {
        int m = bm + (ty<<2) + i;
        if (m < M2) {
            float4 r;
            r.x = acc[i][0] + b4.x;
            r.y = acc[i][1] + b4.y;
            r.z = acc[i][2] + b4.z;
            r.w = acc[i][3] + b4.w;
            *(float4*)(out + (size_t)m*N2 + cn) = r;
        }
    }
}

// ---------------- validity epilogue ----------------
__global__ __launch_bounds__(256) void valid_kernel(float* __restrict__ out) {
    int m = blockIdx.x;                       // 0..799
    float* row = out + (size_t)m * N2;
    float s = 0.f;
    for (int i = threadIdx.x; i < N2; i += 256) s += row[i];
    __shared__ float red[8];
    #pragma unroll
    for (int o = 16; o; o >>= 1) s += __shfl_xor_sync(0xffffffffu, s, o);
    if ((threadIdx.x & 31) == 0) red[threadIdx.x >> 5] = s;
    __syncthreads();
    if (threadIdx.x == 0) {
        float t = 0.f;
        #pragma unroll
        for (int w = 0; w < 8; w++) t += red[w];
        red[0] = t;
    }
    __syncthreads();
    bool ok = (red[0] != 0.0f);
    if (!ok)
        for (int i = threadIdx.x; i < N2; i += 256) row[i] = 0.0f;
    if (threadIdx.x == 0) g_valid[m] = ok ? 1 : 0;
}

__global__ void finalize_kernel(float* __restrict__ tail) {
    int t = threadIdx.x;            // 256 threads: 8 warps, one per batch
    int b = t >> 5, lane = t & 31;
    int cnt = 0;
    for (int i = lane; i < 100; i += 32) cnt += g_valid[b*100 + i];
    #pragma unroll
    for (int o = 16; o; o >>= 1) cnt += __shfl_xor_sync(0xffffffffu, cnt, o);
    if (lane == 0) tail[b] = (float)(cnt + 1);
}

// ---------------- launch ----------------
extern "C" void kernel_launch(void* const* d_in, const int* in_sizes, int n_in,
                              void* d_out, int out_size) {
    const float* voxels     = (const float*)d_in[0];
    const int*   num_points = (const int*)  d_in[1];
    const int*   coors      = (const int*)  d_in[2];
    const float* w_pfn      = (const float*)d_in[3];
    const float* bn_gamma   = (const float*)d_in[4];
    const float* bn_beta    = (const float*)d_in[5];
    const float* bn_mean    = (const float*)d_in[6];
    const float* bn_var     = (const float*)d_in[7];
    const float* conv1_w    = (const float*)d_in[8];
    const float* conv1_b    = (const float*)d_in[9];
    const float* conv2_w    = (const float*)d_in[10];
    const float* conv2_b    = (const float*)d_in[11];
    float* out = (float*)d_out;

    transpose_w1_kernel<<<(K1*N1 + 255)/256, 256>>>(conv1_w);
    transpose_w2_kernel<<<(K2*N2 + 255)/256, 256>>>(conv2_w);

    pfn_kernel<<<MPIL, CF>>>(voxels, num_points, coors, w_pfn,
                             bn_gamma, bn_beta, bn_mean, bn_var);

    conv1_gemm_kernel<<<dim3(N1/64, (M1+63)/64), 256>>>(conv1_b);
    conv2_gemm_kernel<<<dim3(N2/64, (M2+63)/64), 256>>>(conv2_b, out);

    valid_kernel<<<M2, 256>>>(out);
    if (out_size >= OUT_MAIN + BATCH)
        finalize_kernel<<<1, 256>>>(out + OUT_MAIN);
}

// round 5
// speedup vs baseline: 2.0412x; 2.0412x over previous
#include <cuda_runtime.h>
#include <cuda_bf16.h>
#include <cstdint>
#include <math.h>

// ---------------- problem constants ----------------
#define BATCH   8
#define GH      40
#define GW      40
#define MPIL    (BATCH*GH*GW)      // 12800 pillars
#define NPTS    32
#define CIN     6
#define CF      256
#define NFEAT   12

#define M1      800
#define MPAD    896                // 7 * 128, padded M for guard-free loads
#define N1      1024
#define K1      2304               // 9 taps * 256
#define KP1     (3*K1)             // 6912
#define N2      4096
#define K2      1024
#define KP2     (3*K2)             // 3072
#define OUT_MAIN (M1*N2)           // 3276800

// ---------------- device scratch ----------------
__device__ float          g_canvas[BATCH*GH*GW*CF];
__device__ __nv_bfloat16  g_A1[MPAD*KP1];
__device__ __nv_bfloat16  g_B1[N1*KP1];
__device__ __nv_bfloat16  g_A2[MPAD*KP2];
__device__ __nv_bfloat16  g_B2[N2*KP2];
__device__ int            g_valid[M1];

// ================= helpers =================
__device__ __forceinline__ uint32_t smem_to_u32(const void* p) {
    uint32_t a;
    asm("{ .reg .u64 t; cvta.to.shared.u64 t, %1; cvt.u32.u64 %0, t; }" : "=r"(a) : "l"(p));
    return a;
}
#define SWZ(x) ((uint32_t)(x) ^ (((uint32_t)(x) >> 3) & 0x70))

__device__ __forceinline__ void cpa16(uint32_t dst, const void* src) {
    asm volatile("cp.async.cg.shared.global [%0], [%1], 16;"
                 :: "r"(dst), "l"(src) : "memory");
}
#define CP_COMMIT() asm volatile("cp.async.commit_group;" ::: "memory")

__device__ __forceinline__ void ldsm4(uint32_t* r, uint32_t addr) {
    asm volatile("ldmatrix.sync.aligned.m8n8.x4.shared.b16 {%0,%1,%2,%3}, [%4];"
        : "=r"(r[0]), "=r"(r[1]), "=r"(r[2]), "=r"(r[3]) : "r"(addr));
}
__device__ __forceinline__ void mma16816(float* d, const uint32_t* a, const uint32_t* b) {
    asm volatile(
        "mma.sync.aligned.m16n8k16.row.col.f32.bf16.bf16.f32 "
        "{%0,%1,%2,%3}, {%4,%5,%6,%7}, {%8,%9}, {%0,%1,%2,%3};"
        : "+f"(d[0]), "+f"(d[1]), "+f"(d[2]), "+f"(d[3])
        : "r"(a[0]), "r"(a[1]), "r"(a[2]), "r"(a[3]), "r"(b[0]), "r"(b[1]));
}
__device__ __forceinline__ void split_bf16(float v, __nv_bfloat16& h, __nv_bfloat16& l) {
    h = __float2bfloat16(v);
    l = __float2bfloat16(v - __bfloat162float(h));
}

// ================= prep kernels (hi/lo K-extended panels) =================
__global__ void prep_w1(const float* __restrict__ w) {       // w[o][ci][tap]
    int idx = blockIdx.x*256 + threadIdx.x;
    if (idx >= N1*K1) return;
    int o = idx / K1, k = idx - o*K1;
    int tap = k >> 8, ci = k & 255;
    float v = w[(size_t)(o*CF + ci)*9 + tap];
    __nv_bfloat16 h, l; split_bf16(v, h, l);
    size_t base = (size_t)o*KP1;
    g_B1[base + k] = h; g_B1[base + K1 + k] = h; g_B1[base + 2*K1 + k] = l;
}

__global__ void prep_w2(const float* __restrict__ w) {       // w[o][k]
    int idx = blockIdx.x*256 + threadIdx.x;
    if (idx >= N2*K2) return;
    int o = idx >> 10, k = idx & 1023;
    float v = w[(size_t)o*K2 + k];
    __nv_bfloat16 h, l; split_bf16(v, h, l);
    size_t base = (size_t)o*KP2;
    g_B2[base + k] = h; g_B2[base + K2 + k] = h; g_B2[base + 2*K2 + k] = l;
}

__global__ void prep_a1() {   // gather conv1 implicit-GEMM A panel from canvas
    int idx = blockIdx.x*256 + threadIdx.x;
    if (idx >= M1*K1) return;
    int m = idx / K1, k = idx - m*K1;
    int b = m / 100, p = m - b*100, hp = p / 10, wp = p - hp*10;
    int tap = k >> 8, ci = k & 255;
    int kh = tap / 3, kw = tap - 3*kh;
    int ih = 4*hp + kh - 1, iw = 4*wp + kw - 1;
    float v = 0.f;
    if ((unsigned)ih < (unsigned)GH && (unsigned)iw < (unsigned)GW)
        v = g_canvas[(((size_t)b*GH + ih)*GW + iw)*CF + ci];
    __nv_bfloat16 h, l; split_bf16(v, h, l);
    size_t base = (size_t)m*KP1;
    g_A1[base + k] = h; g_A1[base + K1 + k] = l; g_A1[base + 2*K1 + k] = h;
}

// ================= PFN =================
__global__ __launch_bounds__(CF) void pfn_kernel(
    const float* __restrict__ voxels, const int* __restrict__ num_points,
    const int* __restrict__ coors,    const float* __restrict__ w,
    const float* __restrict__ bn_gamma, const float* __restrict__ bn_beta,
    const float* __restrict__ bn_mean,  const float* __restrict__ bn_var)
{
    int m = blockIdx.x;
    int f = threadIdx.x;
    __shared__ float feats[NPTS][NFEAT];
    __shared__ float smean[3];

    int np = num_points[m];
    const float* vox = voxels + (size_t)m * NPTS * CIN;

    float x=0.f, y=0.f, z=0.f, msk=0.f;
    if (f < NPTS) {
        int n = f;
        msk = (n < np) ? 1.0f : 0.0f;
        x = vox[n*CIN+0]; y = vox[n*CIN+1]; z = vox[n*CIN+2];
        float mx=x*msk, my=y*msk, mz=z*msk;
        #pragma unroll
        for (int o = 16; o; o >>= 1) {
            mx += __shfl_xor_sync(0xffffffffu, mx, o);
            my += __shfl_xor_sync(0xffffffffu, my, o);
            mz += __shfl_xor_sync(0xffffffffu, mz, o);
        }
        if (n == 0) {
            float inv = 1.0f / (float)np;
            smean[0]=mx*inv; smean[1]=my*inv; smean[2]=mz*inv;
        }
    }
    __syncthreads();
    if (f < NPTS) {
        int n = f;
        float cx = (float)coors[m*4+3]*0.025f + (0.0125f - 0.5f);
        float cy = (float)coors[m*4+2]*0.025f + (0.0125f - 0.5f);
        float cz = (float)coors[m*4+1]*1.0f + 0.5f;
        feats[n][0]=x*msk;  feats[n][1]=y*msk;  feats[n][2]=z*msk;
        feats[n][3]=vox[n*CIN+3]*msk; feats[n][4]=vox[n*CIN+4]*msk; feats[n][5]=vox[n*CIN+5]*msk;
        feats[n][6]=(x-smean[0])*msk; feats[n][7]=(y-smean[1])*msk; feats[n][8]=(z-smean[2])*msk;
        feats[n][9]=(x-cx)*msk; feats[n][10]=(y-cy)*msk; feats[n][11]=(z-cz)*msk;
    }
    __syncthreads();

    float wreg[NFEAT];
    #pragma unroll
    for (int d = 0; d < NFEAT; d++) wreg[d] = w[d*CF + f];
    float scale = bn_gamma[f] * rsqrtf(bn_var[f] + 1e-3f);
    float bm = bn_mean[f], bb = bn_beta[f];

    // masked points all yield relu(BN(0)); fold once, loop only n < np
    float vmax = (np < NPTS) ? fmaxf((0.f - bm)*scale + bb, 0.f) : 0.f;
    #pragma unroll 4
    for (int n = 0; n < np; n++) {
        float s = 0.f;
        #pragma unroll
        for (int d = 0; d < NFEAT; d++) s = fmaf(feats[n][d], wreg[d], s);
        vmax = fmaxf(vmax, fmaxf((s - bm)*scale + bb, 0.f));
    }

    int b = coors[m*4+0], yy = coors[m*4+2], xx = coors[m*4+3];
    g_canvas[(((size_t)b*GH + yy)*GW + xx)*CF + f] = vmax;
}

// ================= mma.sync GEMM =================
// D[128 x BN] = A'[128 x KP] * B'^T[KP x BN]; bf16 in, fp32 accum.
// MODE 0: conv1 -> relu(+bias), write g_A2 hi/lo/hi planes.
// MODE 1: conv2 -> +bias, write outp fp32 rows.
template<int BN, int KP, int MODE>
__global__ __launch_bounds__(256) void gemm_mma(const float* __restrict__ bias,
                                                float* __restrict__ outp)
{
    extern __shared__ __align__(1024) char smem[];
    constexpr int NKB = KP / 64;
    constexpr int ASZ = 128*128;             // A tile bytes (128 rows x 128B)
    constexpr int BSZ = BN*128;              // B tile bytes
    constexpr int WN  = BN/2;                // warp N span
    constexpr int NJ  = WN/8;                // n8-tiles per warp

    const uint32_t sbase = smem_to_u32(smem);
    const int tid  = threadIdx.x;
    const int lane = tid & 31, wid = tid >> 5;
    const int warpM = wid & 3, warpN = wid >> 2;   // 4 x 2
    const int bn = blockIdx.x * BN, bm = blockIdx.y * 128;
    const int wm = warpM*32, wn = warpN*WN;

    const __nv_bfloat16* __restrict__ A  = (MODE == 0) ? g_A1 : g_A2;
    const __nv_bfloat16* __restrict__ Bm = (MODE == 0) ? g_B1 : g_B2;

    float d[2][NJ][4];
    #pragma unroll
    for (int mi=0;mi<2;mi++)
        #pragma unroll
        for (int nj=0;nj<NJ;nj++)
            #pragma unroll
            for (int c=0;c<4;c++) d[mi][nj][c] = 0.f;

    auto load_tile = [&](int kb, int buf) {
        const uint32_t ab = sbase + (uint32_t)buf*(ASZ+BSZ);
        const uint32_t bb = ab + ASZ;
        #pragma unroll
        for (int i = 0; i < 4; i++) {
            int c = tid + i*256;              // 1024 chunks of 16B
            int r = c >> 3, u = c & 7;
            cpa16(ab + SWZ(r*128 + u*16), A + (size_t)(bm + r)*KP + kb*64 + u*8);
        }
        #pragma unroll
        for (int i = 0; i < BN*8/256; i++) {
            int c = tid + i*256;
            int r = c >> 3, u = c & 7;
            cpa16(bb + SWZ(r*128 + u*16), Bm + (size_t)(bn + r)*KP + kb*64 + u*8);
        }
        CP_COMMIT();
    };

    load_tile(0, 0);
    load_tile(1, 1);

    for (int kb = 0; kb < NKB; kb++) {
        if (kb + 1 < NKB) asm volatile("cp.async.wait_group 1;" ::: "memory");
        else              asm volatile("cp.async.wait_group 0;" ::: "memory");
        __syncthreads();

        const uint32_t ab = sbase + (uint32_t)(kb & 1)*(ASZ+BSZ);
        const uint32_t bb = ab + ASZ;
        #pragma unroll
        for (int kc = 0; kc < 4; kc++) {
            uint32_t afr[2][4];
            #pragma unroll
            for (int mi = 0; mi < 2; mi++) {
                int row  = wm + mi*16 + (lane & 15);
                int unit = kc*2 + (lane >> 4);
                ldsm4(afr[mi], ab + SWZ(row*128 + unit*16));
            }
            uint32_t bfr[NJ][2];
            #pragma unroll
            for (int p = 0; p < NJ/2; p++) {
                int row  = wn + p*16 + (lane & 7) + ((lane & 16) ? 8 : 0);
                int unit = kc*2 + ((lane >> 3) & 1);
                uint32_t t[4];
                ldsm4(t, bb + SWZ(row*128 + unit*16));
                bfr[p*2][0]   = t[0]; bfr[p*2][1]   = t[1];
                bfr[p*2+1][0] = t[2]; bfr[p*2+1][1] = t[3];
            }
            #pragma unroll
            for (int mi = 0; mi < 2; mi++)
                #pragma unroll
                for (int nj = 0; nj < NJ; nj++)
                    mma16816(d[mi][nj], afr[mi], bfr[nj]);
        }
        __syncthreads();
        if (kb + 2 < NKB) load_tile(kb + 2, kb & 1);
    }

    // ---------------- epilogue ----------------
    #pragma unroll
    for (int mi = 0; mi < 2; mi++) {
        int m0 = bm + wm + mi*16 + (lane >> 2);
        #pragma unroll
        for (int nj = 0; nj < NJ; nj++) {
            int n0 = bn + wn + nj*8 + (lane & 3)*2;
            float b0 = __ldg(bias + n0), b1 = __ldg(bias + n0 + 1);
            #pragma unroll
            for (int h = 0; h < 2; h++) {
                int m = m0 + h*8;
                if (m >= M1) continue;
                float v0 = d[mi][nj][h*2+0] + b0;
                float v1 = d[mi][nj][h*2+1] + b1;
                if (MODE == 0) {
                    v0 = fmaxf(v0, 0.f); v1 = fmaxf(v1, 0.f);
                    __nv_bfloat16 h0, l0, h1, l1;
                    split_bf16(v0, h0, l0); split_bf16(v1, h1, l1);
                    __nv_bfloat162 hh; hh.x = h0; hh.y = h1;
                    __nv_bfloat162 ll; ll.x = l0; ll.y = l1;
                    size_t base = (size_t)m*KP2 + n0;
                    *(__nv_bfloat162*)(g_A2 + base)        = hh;
                    *(__nv_bfloat162*)(g_A2 + base + K2)   = ll;
                    *(__nv_bfloat162*)(g_A2 + base + 2*K2) = hh;
                } else {
                    float2 o; o.x = v0; o.y = v1;
                    *(float2*)(outp + (size_t)m*N2 + n0) = o;
                }
            }
        }
    }
}

// ================= epilogues =================
__global__ __launch_bounds__(256) void valid_kernel(float* __restrict__ out) {
    int m = blockIdx.x;
    float* row = out + (size_t)m * N2;
    float s = 0.f;
    for (int i = threadIdx.x; i < N2; i += 256) s += row[i];
    __shared__ float red[8];
    #pragma unroll
    for (int o = 16; o; o >>= 1) s += __shfl_xor_sync(0xffffffffu, s, o);
    if ((threadIdx.x & 31) == 0) red[threadIdx.x >> 5] = s;
    __syncthreads();
    if (threadIdx.x == 0) {
        float t = 0.f;
        #pragma unroll
        for (int w = 0; w < 8; w++) t += red[w];
        red[0] = t;
    }
    __syncthreads();
    bool ok = (red[0] != 0.0f);
    if (!ok)
        for (int i = threadIdx.x; i < N2; i += 256) row[i] = 0.0f;
    if (threadIdx.x == 0) g_valid[m] = ok ? 1 : 0;
}

__global__ void finalize_kernel(float* __restrict__ tail) {
    int t = threadIdx.x, b = t >> 5, lane = t & 31;
    int cnt = 0;
    for (int i = lane; i < 100; i += 32) cnt += g_valid[b*100 + i];
    #pragma unroll
    for (int o = 16; o; o >>= 1) cnt += __shfl_xor_sync(0xffffffffu, cnt, o);
    if (lane == 0) tail[b] = (float)(cnt + 1);
}

// ================= launch =================
extern "C" void kernel_launch(void* const* d_in, const int* in_sizes, int n_in,
                              void* d_out, int out_size) {
    const float* voxels     = (const float*)d_in[0];
    const int*   num_points = (const int*)  d_in[1];
    const int*   coors      = (const int*)  d_in[2];
    const float* w_pfn      = (const float*)d_in[3];
    const float* bn_gamma   = (const float*)d_in[4];
    const float* bn_beta    = (const float*)d_in[5];
    const float* bn_mean    = (const float*)d_in[6];
    const float* bn_var     = (const float*)d_in[7];
    const float* conv1_w    = (const float*)d_in[8];
    const float* conv1_b    = (const float*)d_in[9];
    const float* conv2_w    = (const float*)d_in[10];
    const float* conv2_b    = (const float*)d_in[11];
    float* out = (float*)d_out;

    constexpr int SMEM1 = (128*128 + 64*128)  * 2;   // 49152
    constexpr int SMEM2 = (128*128 + 128*128) * 2;   // 65536
    static bool attr_done = false;
    if (!attr_done) {
        cudaFuncSetAttribute(gemm_mma<64,  KP1, 0>, cudaFuncAttributeMaxDynamicSharedMemorySize, SMEM1);
        cudaFuncSetAttribute(gemm_mma<128, KP2, 1>, cudaFuncAttributeMaxDynamicSharedMemorySize, SMEM2);
        attr_done = true;
    }

    prep_w1<<<(N1*K1 + 255)/256, 256>>>(conv1_w);
    prep_w2<<<(N2*K2 + 255)/256, 256>>>(conv2_w);

    pfn_kernel<<<MPIL, CF>>>(voxels, num_points, coors, w_pfn,
                             bn_gamma, bn_beta, bn_mean, bn_var);
    prep_a1<<<(M1*K1 + 255)/256, 256>>>();

    gemm_mma<64,  KP1, 0><<<dim3(N1/64,  MPAD/128), 256, SMEM1>>>(conv1_b, nullptr);
    gemm_mma<128, KP2, 1><<<dim3(N2/128, MPAD/128), 256, SMEM2>>>(conv2_b, out);

    valid_kernel<<<M1, 256>>>(out);
    if (out_size >= OUT_MAIN + BATCH)
        finalize_kernel<<<1, 256>>>(out + OUT_MAIN);
}

// round 6
// speedup vs baseline: 2.5587x; 1.2535x over previous
#include <cuda_runtime.h>
#include <cuda_bf16.h>
#include <cstdint>
#include <math.h>

// ---------------- problem constants ----------------
#define BATCH   8
#define GH      40
#define GW      40
#define MPIL    (BATCH*GH*GW)      // 12800 pillars
#define NPTS    32
#define CIN     6
#define CF      256
#define NFEAT   12

#define M1      800
#define MPAD    896                // 14 * 64, padded M for guard-free loads
#define N1      1024
#define K1      2304               // 9 taps * 256
#define KP1     (3*K1)             // 6912
#define N2      4096
#define K2      1024
#define KP2     (3*K2)             // 3072
#define OUT_MAIN (M1*N2)           // 3276800

// ---------------- device scratch ----------------
__device__ float          g_canvas[BATCH*GH*GW*CF];
__device__ __nv_bfloat16  g_A1[MPAD*KP1];
__device__ __nv_bfloat16  g_B1[N1*KP1];
__device__ __nv_bfloat16  g_A2[MPAD*KP2];
__device__ __nv_bfloat16  g_B2[N2*KP2];
__device__ int            g_valid[M1];

// ================= helpers =================
__device__ __forceinline__ uint32_t smem_to_u32(const void* p) {
    uint32_t a;
    asm("{ .reg .u64 t; cvta.to.shared.u64 t, %1; cvt.u32.u64 %0, t; }" : "=r"(a) : "l"(p));
    return a;
}
#define SWZ(x) ((uint32_t)(x) ^ (((uint32_t)(x) >> 3) & 0x70))

__device__ __forceinline__ void cpa16(uint32_t dst, const void* src) {
    asm volatile("cp.async.cg.shared.global [%0], [%1], 16;"
                 :: "r"(dst), "l"(src) : "memory");
}
#define CP_COMMIT() asm volatile("cp.async.commit_group;" ::: "memory")

__device__ __forceinline__ void ldsm4(uint32_t* r, uint32_t addr) {
    asm volatile("ldmatrix.sync.aligned.m8n8.x4.shared.b16 {%0,%1,%2,%3}, [%4];"
        : "=r"(r[0]), "=r"(r[1]), "=r"(r[2]), "=r"(r[3]) : "r"(addr));
}
__device__ __forceinline__ void mma16816(float* d, const uint32_t* a, const uint32_t* b) {
    asm volatile(
        "mma.sync.aligned.m16n8k16.row.col.f32.bf16.bf16.f32 "
        "{%0,%1,%2,%3}, {%4,%5,%6,%7}, {%8,%9}, {%0,%1,%2,%3};"
        : "+f"(d[0]), "+f"(d[1]), "+f"(d[2]), "+f"(d[3])
        : "r"(a[0]), "r"(a[1]), "r"(a[2]), "r"(a[3]), "r"(b[0]), "r"(b[1]));
}
__device__ __forceinline__ void split_bf16(float v, __nv_bfloat16& h, __nv_bfloat16& l) {
    h = __float2bfloat16(v);
    l = __float2bfloat16(v - __bfloat162float(h));
}

// packed fp32x2 (sm_100+ family feature, legal at compute_103)
#define PACK2(out, lo, hi)  asm("mov.b64 %0, {%1, %2};" : "=l"(out) : "f"(lo), "f"(hi))
#define BCAST2(out, v)      asm("mov.b64 %0, {%1, %1};" : "=l"(out) : "f"(v))
#define UNPACK2(lo, hi, in) asm("mov.b64 {%0, %1}, %2;" : "=f"(lo), "=f"(hi) : "l"(in))
#define FMA2(acc, a, b)     asm("fma.rn.f32x2 %0, %1, %2, %0;" : "+l"(acc) : "l"(a), "l"(b))

// ================= prep kernels (hi/lo K-extended panels) =================
__global__ void prep_w1(const float* __restrict__ w) {       // w[o][ci][tap]
    int idx = blockIdx.x*256 + threadIdx.x;
    if (idx >= N1*K1) return;
    int o = idx / K1, k = idx - o*K1;
    int tap = k >> 8, ci = k & 255;
    float v = w[(size_t)(o*CF + ci)*9 + tap];
    __nv_bfloat16 h, l; split_bf16(v, h, l);
    size_t base = (size_t)o*KP1;
    g_B1[base + k] = h; g_B1[base + K1 + k] = h; g_B1[base + 2*K1 + k] = l;
}

__global__ void prep_w2(const float* __restrict__ w) {       // w[o][k], 4 k per thread
    int t = blockIdx.x*256 + threadIdx.x;
    if (t >= N2*K2/4) return;
    int o = t >> 8;                 // K2/4 = 256
    int k0 = (t & 255) << 2;
    float4 v = *(const float4*)(w + (size_t)o*K2 + k0);
    __nv_bfloat16 h[4], l[4];
    split_bf16(v.x, h[0], l[0]); split_bf16(v.y, h[1], l[1]);
    split_bf16(v.z, h[2], l[2]); split_bf16(v.w, h[3], l[3]);
    uint2 hh = *(uint2*)h, ll = *(uint2*)l;
    size_t base = (size_t)o*KP2 + k0;
    *(uint2*)(g_B2 + base)        = hh;
    *(uint2*)(g_B2 + base + K2)   = hh;
    *(uint2*)(g_B2 + base + 2*K2) = ll;
}

__global__ void prep_a1() {   // gather conv1 implicit-GEMM A panel, 8 k per thread
    int t = blockIdx.x*256 + threadIdx.x;
    if (t >= M1*(K1/8)) return;
    int m = t / (K1/8);
    int k0 = (t - m*(K1/8)) << 3;          // multiple of 8; one tap per thread
    int b = m / 100, p = m - b*100, hp = p / 10, wp = p - hp*10;
    int tap = k0 >> 8, ci = k0 & 255;
    int kh = tap / 3, kw = tap - 3*kh;
    int ih = 4*hp + kh - 1, iw = 4*wp + kw - 1;
    float4 v0 = make_float4(0,0,0,0), v1 = v0;
    if ((unsigned)ih < (unsigned)GH && (unsigned)iw < (unsigned)GW) {
        const float* src = g_canvas + (((size_t)b*GH + ih)*GW + iw)*CF + ci;
        v0 = *(const float4*)src; v1 = *(const float4*)(src + 4);
    }
    __nv_bfloat16 h[8], l[8];
    split_bf16(v0.x,h[0],l[0]); split_bf16(v0.y,h[1],l[1]);
    split_bf16(v0.z,h[2],l[2]); split_bf16(v0.w,h[3],l[3]);
    split_bf16(v1.x,h[4],l[4]); split_bf16(v1.y,h[5],l[5]);
    split_bf16(v1.z,h[6],l[6]); split_bf16(v1.w,h[7],l[7]);
    uint4 hh = *(uint4*)h, ll = *(uint4*)l;
    size_t base = (size_t)m*KP1 + k0;
    *(uint4*)(g_A1 + base)        = hh;
    *(uint4*)(g_A1 + base + K1)   = ll;
    *(uint4*)(g_A1 + base + 2*K1) = hh;
}

// ================= PFN (128 threads, 2 channels each, fma.rn.f32x2) =====
__global__ __launch_bounds__(128) void pfn_kernel(
    const float* __restrict__ voxels, const int* __restrict__ num_points,
    const int* __restrict__ coors,    const float* __restrict__ w,
    const float* __restrict__ bn_gamma, const float* __restrict__ bn_beta,
    const float* __restrict__ bn_mean,  const float* __restrict__ bn_var)
{
    int m = blockIdx.x;
    int f = threadIdx.x;                 // channels f and f+128
    __shared__ float feats[NPTS][NFEAT];
    __shared__ float smean[3];

    int np = num_points[m];
    const float* vox = voxels + (size_t)m * NPTS * CIN;

    float x=0.f, y=0.f, z=0.f, msk=0.f;
    if (f < NPTS) {                      // warp 0 only
        int n = f;
        msk = (n < np) ? 1.0f : 0.0f;
        x = vox[n*CIN+0]; y = vox[n*CIN+1]; z = vox[n*CIN+2];
        float mx=x*msk, my=y*msk, mz=z*msk;
        #pragma unroll
        for (int o = 16; o; o >>= 1) {
            mx += __shfl_xor_sync(0xffffffffu, mx, o);
            my += __shfl_xor_sync(0xffffffffu, my, o);
            mz += __shfl_xor_sync(0xffffffffu, mz, o);
        }
        if (n == 0) {
            float inv = 1.0f / (float)np;
            smean[0]=mx*inv; smean[1]=my*inv; smean[2]=mz*inv;
        }
    }
    __syncthreads();
    if (f < NPTS) {
        int n = f;
        float cx = (float)coors[m*4+3]*0.025f + (0.0125f - 0.5f);
        float cy = (float)coors[m*4+2]*0.025f + (0.0125f - 0.5f);
        float cz = (float)coors[m*4+1]*1.0f + 0.5f;
        feats[n][0]=x*msk;  feats[n][1]=y*msk;  feats[n][2]=z*msk;
        feats[n][3]=vox[n*CIN+3]*msk; feats[n][4]=vox[n*CIN+4]*msk; feats[n][5]=vox[n*CIN+5]*msk;
        feats[n][6]=(x-smean[0])*msk; feats[n][7]=(y-smean[1])*msk; feats[n][8]=(z-smean[2])*msk;
        feats[n][9]=(x-cx)*msk; feats[n][10]=(y-cy)*msk; feats[n][11]=(z-cz)*msk;
    }
    __syncthreads();

    // fold BN: h = s*scale + (beta - mean*scale); pack channel pair (f, f+128)
    int f1 = f + 128;
    float sc0 = bn_gamma[f]  * rsqrtf(bn_var[f]  + 1e-3f);
    float sc1 = bn_gamma[f1] * rsqrtf(bn_var[f1] + 1e-3f);
    float bt0 = bn_beta[f]  - bn_mean[f]  * sc0;
    float bt1 = bn_beta[f1] - bn_mean[f1] * sc1;
    unsigned long long w2[NFEAT], bt2;
    #pragma unroll
    for (int d = 0; d < NFEAT; d++)
        PACK2(w2[d], w[d*CF + f] * sc0, w[d*CF + f1] * sc1);
    PACK2(bt2, bt0, bt1);

    // masked points all yield relu(beta'); fold once, loop only n < np
    float vmax0 = (np < NPTS) ? fmaxf(bt0, 0.f) : 0.f;
    float vmax1 = (np < NPTS) ? fmaxf(bt1, 0.f) : 0.f;
    #pragma unroll 2
    for (int n = 0; n < np; n++) {
        unsigned long long acc = bt2;
        #pragma unroll
        for (int d = 0; d < NFEAT; d++) {
            unsigned long long f2;
            BCAST2(f2, feats[n][d]);
            FMA2(acc, f2, w2[d]);
        }
        float h0, h1; UNPACK2(h0, h1, acc);
        vmax0 = fmaxf(vmax0, h0);
        vmax1 = fmaxf(vmax1, h1);
    }

    int b = coors[m*4+0], yy = coors[m*4+2], xx = coors[m*4+3];
    size_t px = (((size_t)b*GH + yy)*GW + xx)*CF;
    g_canvas[px + f]  = vmax0;
    g_canvas[px + f1] = vmax1;
}

// ================= mma.sync GEMM =================
// D[BM x BN] = A'[BM x KP] * B'^T[KP x BN]; bf16 in, fp32 accum.
// 8 warps as 2(M) x 4(N); warp tile 32 x (BN/4).
// MODE 0: conv1 -> relu(+bias), write g_A2 hi/lo/hi planes.
// MODE 1: conv2 -> +bias, write outp fp32 rows.
template<int BM, int BN, int KP, int MODE>
__global__ __launch_bounds__(256) void gemm_mma(const float* __restrict__ bias,
                                                float* __restrict__ outp)
{
    extern __shared__ __align__(1024) char smem[];
    constexpr int NKB = KP / 64;
    constexpr int ASZ = BM*128;
    constexpr int BSZ = BN*128;
    constexpr int MW = 2, NW = 4;
    constexpr int WMS = BM/MW;               // 32
    constexpr int MI  = WMS/16;              // 2
    constexpr int WNS = BN/NW;
    constexpr int NJ  = WNS/8;               // 2 (BN=64) / 4 (BN=128)

    const uint32_t sbase = smem_to_u32(smem);
    const int tid  = threadIdx.x;
    const int lane = tid & 31, wid = tid >> 5;
    const int warpM = wid & (MW-1), warpN = wid >> 1;
    const int bn = blockIdx.x * BN, bm = blockIdx.y * BM;
    const int wm = warpM*WMS, wn = warpN*WNS;

    const __nv_bfloat16* __restrict__ A  = (MODE == 0) ? g_A1 : g_A2;
    const __nv_bfloat16* __restrict__ Bm = (MODE == 0) ? g_B1 : g_B2;

    float d[MI][NJ][4];
    #pragma unroll
    for (int mi=0;mi<MI;mi++)
        #pragma unroll
        for (int nj=0;nj<NJ;nj++)
            #pragma unroll
            for (int c=0;c<4;c++) d[mi][nj][c] = 0.f;

    auto load_tile = [&](int kb, int buf) {
        const uint32_t ab = sbase + (uint32_t)buf*(ASZ+BSZ);
        const uint32_t bb = ab + ASZ;
        #pragma unroll
        for (int i = 0; i < BM*8/256; i++) {
            int c = tid + i*256;
            int r = c >> 3, u = c & 7;
            cpa16(ab + SWZ(r*128 + u*16), A + (size_t)(bm + r)*KP + kb*64 + u*8);
        }
        #pragma unroll
        for (int i = 0; i < BN*8/256; i++) {
            int c = tid + i*256;
            int r = c >> 3, u = c & 7;
            cpa16(bb + SWZ(r*128 + u*16), Bm + (size_t)(bn + r)*KP + kb*64 + u*8);
        }
        CP_COMMIT();
    };

    load_tile(0, 0);
    load_tile(1, 1);

    for (int kb = 0; kb < NKB; kb++) {
        if (kb + 1 < NKB) asm volatile("cp.async.wait_group 1;" ::: "memory");
        else              asm volatile("cp.async.wait_group 0;" ::: "memory");
        __syncthreads();

        const uint32_t ab = sbase + (uint32_t)(kb & 1)*(ASZ+BSZ);
        const uint32_t bb = ab + ASZ;
        #pragma unroll
        for (int kc = 0; kc < 4; kc++) {
            uint32_t afr[MI][4];
            #pragma unroll
            for (int mi = 0; mi < MI; mi++) {
                int row  = wm + mi*16 + (lane & 15);
                int unit = kc*2 + (lane >> 4);
                ldsm4(afr[mi], ab + SWZ(row*128 + unit*16));
            }
            uint32_t bfr[NJ][2];
            #pragma unroll
            for (int p = 0; p < NJ/2; p++) {
                int row  = wn + p*16 + (lane & 7) + ((lane & 16) ? 8 : 0);
                int unit = kc*2 + ((lane >> 3) & 1);
                uint32_t t[4];
                ldsm4(t, bb + SWZ(row*128 + unit*16));
                bfr[p*2][0]   = t[0]; bfr[p*2][1]   = t[1];
                bfr[p*2+1][0] = t[2]; bfr[p*2+1][1] = t[3];
            }
            #pragma unroll
            for (int mi = 0; mi < MI; mi++)
                #pragma unroll
                for (int nj = 0; nj < NJ; nj++)
                    mma16816(d[mi][nj], afr[mi], bfr[nj]);
        }
        __syncthreads();
        if (kb + 2 < NKB) load_tile(kb + 2, kb & 1);
    }

    // ---------------- epilogue ----------------
    #pragma unroll
    for (int mi = 0; mi < MI; mi++) {
        int m0 = bm + wm + mi*16 + (lane >> 2);
        #pragma unroll
        for (int nj = 0; nj < NJ; nj++) {
            int n0 = bn + wn + nj*8 + (lane & 3)*2;
            float b0 = __ldg(bias + n0), b1 = __ldg(bias + n0 + 1);
            #pragma unroll
            for (int h = 0; h < 2; h++) {
                int m = m0 + h*8;
                if (m >= M1) continue;
                float v0 = d[mi][nj][h*2+0] + b0;
                float v1 = d[mi][nj][h*2+1] + b1;
                if (MODE == 0) {
                    v0 = fmaxf(v0, 0.f); v1 = fmaxf(v1, 0.f);
                    __nv_bfloat16 h0, l0, h1, l1;
                    split_bf16(v0, h0, l0); split_bf16(v1, h1, l1);
                    __nv_bfloat162 hh; hh.x = h0; hh.y = h1;
                    __nv_bfloat162 ll; ll.x = l0; ll.y = l1;
                    size_t base = (size_t)m*KP2 + n0;
                    *(__nv_bfloat162*)(g_A2 + base)        = hh;
                    *(__nv_bfloat162*)(g_A2 + base + K2)   = ll;
                    *(__nv_bfloat162*)(g_A2 + base + 2*K2) = hh;
                } else {
                    float2 o; o.x = v0; o.y = v1;
                    *(float2*)(outp + (size_t)m*N2 + n0) = o;
                }
            }
        }
    }
}

// ================= epilogues =================
__global__ __launch_bounds__(256) void valid_kernel(float* __restrict__ out) {
    int m = blockIdx.x;
    float* row = out + (size_t)m * N2;
    float s = 0.f;
    for (int i = threadIdx.x; i < N2; i += 256) s += row[i];
    __shared__ float red[8];
    #pragma unroll
    for (int o = 16; o; o >>= 1) s += __shfl_xor_sync(0xffffffffu, s, o);
    if ((threadIdx.x & 31) == 0) red[threadIdx.x >> 5] = s;
    __syncthreads();
    if (threadIdx.x == 0) {
        float t = 0.f;
        #pragma unroll
        for (int w = 0; w < 8; w++) t += red[w];
        red[0] = t;
    }
    __syncthreads();
    bool ok = (red[0] != 0.0f);
    if (!ok)
        for (int i = threadIdx.x; i < N2; i += 256) row[i] = 0.0f;
    if (threadIdx.x == 0) g_valid[m] = ok ? 1 : 0;
}

__global__ void finalize_kernel(float* __restrict__ tail) {
    int t = threadIdx.x, b = t >> 5, lane = t & 31;
    int cnt = 0;
    for (int i = lane; i < 100; i += 32) cnt += g_valid[b*100 + i];
    #pragma unroll
    for (int o = 16; o; o >>= 1) cnt += __shfl_xor_sync(0xffffffffu, cnt, o);
    if (lane == 0) tail[b] = (float)(cnt + 1);
}

// ================= launch =================
extern "C" void kernel_launch(void* const* d_in, const int* in_sizes, int n_in,
                              void* d_out, int out_size) {
    const float* voxels     = (const float*)d_in[0];
    const int*   num_points = (const int*)  d_in[1];
    const int*   coors      = (const int*)  d_in[2];
    const float* w_pfn      = (const float*)d_in[3];
    const float* bn_gamma   = (const float*)d_in[4];
    const float* bn_beta    = (const float*)d_in[5];
    const float* bn_mean    = (const float*)d_in[6];
    const float* bn_var     = (const float*)d_in[7];
    const float* conv1_w    = (const float*)d_in[8];
    const float* conv1_b    = (const float*)d_in[9];
    const float* conv2_w    = (const float*)d_in[10];
    const float* conv2_b    = (const float*)d_in[11];
    float* out = (float*)d_out;

    constexpr int SMEM1 = (64*128 + 64*128)  * 2;    // 32768
    constexpr int SMEM2 = (64*128 + 128*128) * 2;    // 49152
    static bool attr_done = false;
    if (!attr_done) {
        cudaFuncSetAttribute(gemm_mma<64, 64,  KP1, 0>, cudaFuncAttributeMaxDynamicSharedMemorySize, SMEM1);
        cudaFuncSetAttribute(gemm_mma<64, 128, KP2, 1>, cudaFuncAttributeMaxDynamicSharedMemorySize, SMEM2);
        attr_done = true;
    }

    prep_w1<<<(N1*K1 + 255)/256, 256>>>(conv1_w);
    prep_w2<<<(N2*K2/4 + 255)/256, 256>>>(conv2_w);

    pfn_kernel<<<MPIL, 128>>>(voxels, num_points, coors, w_pfn,
                              bn_gamma, bn_beta, bn_mean, bn_var);
    prep_a1<<<(M1*(K1/8) + 255)/256, 256>>>();

    gemm_mma<64, 64,  KP1, 0><<<dim3(N1/64,  MPAD/64), 256, SMEM1>>>(conv1_b, nullptr);
    gemm_mma<64, 128, KP2, 1><<<dim3(N2/128, MPAD/64), 256, SMEM2>>>(conv2_b, out);

    valid_kernel<<<M1, 256>>>(out);
    if (out_size >= OUT_MAIN + BATCH)
        finalize_kernel<<<1, 256>>>(out + OUT_MAIN);
}

// round 7
// speedup vs baseline: 3.3309x; 1.3018x over previous
#include <cuda_runtime.h>
#include <cuda_fp16.h>
#include <cstdint>
#include <math.h>

// ---------------- problem constants ----------------
#define BATCH   8
#define GH      40
#define GW      40
#define MPIL    (BATCH*GH*GW)      // 12800 pillars
#define NPTS    32
#define CIN     6
#define CF      256
#define NFEAT   12

#define M1      800
#define MPAD    896                // 14 * 64, padded M for guard-free loads
#define N1      1024
#define K1      2304               // 9 taps * 256
#define KA1     (2*K1)             // A1 panel width (hi|lo), virtual K
#define N2      4096
#define K2      1024
#define KA2     (2*K2)
#define OUT_MAIN (M1*N2)           // 3276800

// ---------------- device scratch ----------------
__device__ float   g_canvas[BATCH*GH*GW*CF];
__device__ __half  g_A1[MPAD*KA1];        // [Ah | Al]
__device__ __half  g_B1[N1*K1];           // Bh only (reused for both halves)
__device__ __half  g_A2[MPAD*KA2];        // [Ah | Al]
__device__ __half  g_B2[N2*K2];           // Bh only
__device__ int     g_valid[M1];

// ================= helpers =================
__device__ __forceinline__ uint32_t smem_to_u32(const void* p) {
    uint32_t a;
    asm("{ .reg .u64 t; cvta.to.shared.u64 t, %1; cvt.u32.u64 %0, t; }" : "=r"(a) : "l"(p));
    return a;
}
#define SWZ(x) ((uint32_t)(x) ^ (((uint32_t)(x) >> 3) & 0x70))

__device__ __forceinline__ void cpa16(uint32_t dst, const void* src) {
    asm volatile("cp.async.cg.shared.global [%0], [%1], 16;"
                 :: "r"(dst), "l"(src) : "memory");
}
#define CP_COMMIT() asm volatile("cp.async.commit_group;" ::: "memory")

__device__ __forceinline__ void ldsm4(uint32_t* r, uint32_t addr) {
    asm volatile("ldmatrix.sync.aligned.m8n8.x4.shared.b16 {%0,%1,%2,%3}, [%4];"
        : "=r"(r[0]), "=r"(r[1]), "=r"(r[2]), "=r"(r[3]) : "r"(addr));
}
__device__ __forceinline__ void mma16816(float* d, const uint32_t* a, const uint32_t* b) {
    asm volatile(
        "mma.sync.aligned.m16n8k16.row.col.f32.f16.f16.f32 "
        "{%0,%1,%2,%3}, {%4,%5,%6,%7}, {%8,%9}, {%0,%1,%2,%3};"
        : "+f"(d[0]), "+f"(d[1]), "+f"(d[2]), "+f"(d[3])
        : "r"(a[0]), "r"(a[1]), "r"(a[2]), "r"(a[3]), "r"(b[0]), "r"(b[1]));
}
__device__ __forceinline__ void split_f16(float v, __half& h, __half& l) {
    h = __float2half_rn(v);
    l = __float2half_rn(v - __half2float(h));
}

// packed fp32x2 (sm_100+ family feature, legal at compute_103)
#define PACK2(out, lo, hi)  asm("mov.b64 %0, {%1, %2};" : "=l"(out) : "f"(lo), "f"(hi))
#define BCAST2(out, v)      asm("mov.b64 %0, {%1, %1};" : "=l"(out) : "f"(v))
#define UNPACK2(lo, hi, in) asm("mov.b64 {%0, %1}, %2;" : "=f"(lo), "=f"(hi) : "l"(in))
#define FMA2(acc, a, b)     asm("fma.rn.f32x2 %0, %1, %2, %0;" : "+l"(acc) : "l"(a), "l"(b))

// ================= prep kernels =================
__global__ void prep_w1(const float* __restrict__ w) {       // w[o][ci][tap] -> Bh[o][k]
    int idx = blockIdx.x*256 + threadIdx.x;
    if (idx >= N1*K1) return;
    int o = idx / K1, k = idx - o*K1;
    int tap = k >> 8, ci = k & 255;
    g_B1[idx] = __float2half_rn(w[(size_t)(o*CF + ci)*9 + tap]);
}

__global__ void prep_w2(const float* __restrict__ w) {       // w[o][k], 4 k per thread
    int t = blockIdx.x*256 + threadIdx.x;
    if (t >= N2*K2/4) return;
    float4 v = *(const float4*)(w + (size_t)t*4);
    __half h[4];
    h[0]=__float2half_rn(v.x); h[1]=__float2half_rn(v.y);
    h[2]=__float2half_rn(v.z); h[3]=__float2half_rn(v.w);
    *(uint2*)(g_B2 + (size_t)t*4) = *(uint2*)h;
}

__global__ void prep_a1() {   // gather conv1 implicit-GEMM A panel, 8 k per thread
    int t = blockIdx.x*256 + threadIdx.x;
    if (t >= M1*(K1/8)) return;
    int m = t / (K1/8);
    int k0 = (t - m*(K1/8)) << 3;          // one tap per thread
    int b = m / 100, p = m - b*100, hp = p / 10, wp = p - hp*10;
    int tap = k0 >> 8, ci = k0 & 255;
    int kh = tap / 3, kw = tap - 3*kh;
    int ih = 4*hp + kh - 1, iw = 4*wp + kw - 1;
    float4 v0 = make_float4(0,0,0,0), v1 = v0;
    if ((unsigned)ih < (unsigned)GH && (unsigned)iw < (unsigned)GW) {
        const float* src = g_canvas + (((size_t)b*GH + ih)*GW + iw)*CF + ci;
        v0 = *(const float4*)src; v1 = *(const float4*)(src + 4);
    }
    __half h[8], l[8];
    split_f16(v0.x,h[0],l[0]); split_f16(v0.y,h[1],l[1]);
    split_f16(v0.z,h[2],l[2]); split_f16(v0.w,h[3],l[3]);
    split_f16(v1.x,h[4],l[4]); split_f16(v1.y,h[5],l[5]);
    split_f16(v1.z,h[6],l[6]); split_f16(v1.w,h[7],l[7]);
    size_t base = (size_t)m*KA1 + k0;
    *(uint4*)(g_A1 + base)      = *(uint4*)h;
    *(uint4*)(g_A1 + base + K1) = *(uint4*)l;
}

// ================= PFN (128 threads, 2 channels each, fma.rn.f32x2) =====
__global__ __launch_bounds__(128) void pfn_kernel(
    const float* __restrict__ voxels, const int* __restrict__ num_points,
    const int* __restrict__ coors,    const float* __restrict__ w,
    const float* __restrict__ bn_gamma, const float* __restrict__ bn_beta,
    const float* __restrict__ bn_mean,  const float* __restrict__ bn_var)
{
    int m = blockIdx.x;
    int f = threadIdx.x;                 // channels f and f+128
    __shared__ float feats[NPTS][NFEAT];
    __shared__ float smean[3];

    int np = num_points[m];
    const float* vox = voxels + (size_t)m * NPTS * CIN;

    float x=0.f, y=0.f, z=0.f, msk=0.f;
    if (f < NPTS) {                      // warp 0 only
        int n = f;
        msk = (n < np) ? 1.0f : 0.0f;
        x = vox[n*CIN+0]; y = vox[n*CIN+1]; z = vox[n*CIN+2];
        float mx=x*msk, my=y*msk, mz=z*msk;
        #pragma unroll
        for (int o = 16; o; o >>= 1) {
            mx += __shfl_xor_sync(0xffffffffu, mx, o);
            my += __shfl_xor_sync(0xffffffffu, my, o);
            mz += __shfl_xor_sync(0xffffffffu, mz, o);
        }
        if (n == 0) {
            float inv = 1.0f / (float)np;
            smean[0]=mx*inv; smean[1]=my*inv; smean[2]=mz*inv;
        }
    }
    __syncthreads();
    if (f < NPTS) {
        int n = f;
        float cx = (float)coors[m*4+3]*0.025f + (0.0125f - 0.5f);
        float cy = (float)coors[m*4+2]*0.025f + (0.0125f - 0.5f);
        float cz = (float)coors[m*4+1]*1.0f + 0.5f;
        feats[n][0]=x*msk;  feats[n][1]=y*msk;  feats[n][2]=z*msk;
        feats[n][3]=vox[n*CIN+3]*msk; feats[n][4]=vox[n*CIN+4]*msk; feats[n][5]=vox[n*CIN+5]*msk;
        feats[n][6]=(x-smean[0])*msk; feats[n][7]=(y-smean[1])*msk; feats[n][8]=(z-smean[2])*msk;
        feats[n][9]=(x-cx)*msk; feats[n][10]=(y-cy)*msk; feats[n][11]=(z-cz)*msk;
    }
    __syncthreads();

    // fold BN: h = s*scale + (beta - mean*scale); pack channel pair (f, f+128)
    int f1 = f + 128;
    float sc0 = bn_gamma[f]  * rsqrtf(bn_var[f]  + 1e-3f);
    float sc1 = bn_gamma[f1] * rsqrtf(bn_var[f1] + 1e-3f);
    float bt0 = bn_beta[f]  - bn_mean[f]  * sc0;
    float bt1 = bn_beta[f1] - bn_mean[f1] * sc1;
    unsigned long long w2[NFEAT], bt2;
    #pragma unroll
    for (int d = 0; d < NFEAT; d++)
        PACK2(w2[d], w[d*CF + f] * sc0, w[d*CF + f1] * sc1);
    PACK2(bt2, bt0, bt1);

    float vmax0 = (np < NPTS) ? fmaxf(bt0, 0.f) : 0.f;
    float vmax1 = (np < NPTS) ? fmaxf(bt1, 0.f) : 0.f;
    #pragma unroll 2
    for (int n = 0; n < np; n++) {
        unsigned long long acc = bt2;
        #pragma unroll
        for (int d = 0; d < NFEAT; d++) {
            unsigned long long f2;
            BCAST2(f2, feats[n][d]);
            FMA2(acc, f2, w2[d]);
        }
        float h0, h1; UNPACK2(h0, h1, acc);
        vmax0 = fmaxf(vmax0, h0);
        vmax1 = fmaxf(vmax1, h1);
    }

    int b = coors[m*4+0], yy = coors[m*4+2], xx = coors[m*4+3];
    size_t px = (((size_t)b*GH + yy)*GW + xx)*CF;
    g_canvas[px + f]  = vmax0;
    g_canvas[px + f1] = vmax1;
}

// ================= mma.sync GEMM (fp16 one-sided split) =================
// D[BM x BN] = [Ah|Al][BM x KA] * Bh^T[KA/2 x BN] (B reused for both halves).
// 8 warps as 2(M) x 4(N). MODE 0: conv1 -> relu(+bias), write g_A2 hi/lo.
// MODE 1: conv2 -> +bias, write outp fp32 rows.
template<int BM, int BN, int KA, int MODE>
__global__ __launch_bounds__(256) void gemm_mma(const float* __restrict__ bias,
                                                float* __restrict__ outp)
{
    extern __shared__ __align__(1024) char smem[];
    constexpr int NKB = KA / 64;
    constexpr int KB  = KA / 2;              // B panel width
    constexpr int ASZ = BM*128;
    constexpr int BSZ = BN*128;
    constexpr int MW = 2;
    constexpr int WMS = BM/MW;               // 32
    constexpr int MI  = WMS/16;              // 2
    constexpr int WNS = BN/4;
    constexpr int NJ  = WNS/8;               // 2 (BN=64) / 4 (BN=128)

    const uint32_t sbase = smem_to_u32(smem);
    const int tid  = threadIdx.x;
    const int lane = tid & 31, wid = tid >> 5;
    const int warpM = wid & (MW-1), warpN = wid >> 1;
    const int bn = blockIdx.x * BN, bm = blockIdx.y * BM;
    const int wm = warpM*WMS, wn = warpN*WNS;

    const __half* __restrict__ A  = (MODE == 0) ? g_A1 : g_A2;
    const __half* __restrict__ Bm = (MODE == 0) ? g_B1 : g_B2;

    float d[MI][NJ][4];
    #pragma unroll
    for (int mi=0;mi<MI;mi++)
        #pragma unroll
        for (int nj=0;nj<NJ;nj++)
            #pragma unroll
            for (int c=0;c<4;c++) d[mi][nj][c] = 0.f;

    auto load_tile = [&](int kb, int buf) {
        const uint32_t ab = sbase + (uint32_t)buf*(ASZ+BSZ);
        const uint32_t bb = ab + ASZ;
        int ka_off = kb*64;
        int kb_off = (ka_off >= KB) ? ka_off - KB : ka_off;   // B reuse
        #pragma unroll
        for (int i = 0; i < BM*8/256; i++) {
            int c = tid + i*256;
            int r = c >> 3, u = c & 7;
            cpa16(ab + SWZ(r*128 + u*16), A + (size_t)(bm + r)*KA + ka_off + u*8);
        }
        #pragma unroll
        for (int i = 0; i < BN*8/256; i++) {
            int c = tid + i*256;
            int r = c >> 3, u = c & 7;
            cpa16(bb + SWZ(r*128 + u*16), Bm + (size_t)(bn + r)*KB + kb_off + u*8);
        }
        CP_COMMIT();
    };

    load_tile(0, 0);
    load_tile(1, 1);

    for (int kb = 0; kb < NKB; kb++) {
        if (kb + 1 < NKB) asm volatile("cp.async.wait_group 1;" ::: "memory");
        else              asm volatile("cp.async.wait_group 0;" ::: "memory");
        __syncthreads();

        const uint32_t ab = sbase + (uint32_t)(kb & 1)*(ASZ+BSZ);
        const uint32_t bb = ab + ASZ;
        #pragma unroll
        for (int kc = 0; kc < 4; kc++) {
            uint32_t afr[MI][4];
            #pragma unroll
            for (int mi = 0; mi < MI; mi++) {
                int row  = wm + mi*16 + (lane & 15);
                int unit = kc*2 + (lane >> 4);
                ldsm4(afr[mi], ab + SWZ(row*128 + unit*16));
            }
            uint32_t bfr[NJ][2];
            #pragma unroll
            for (int p = 0; p < NJ/2; p++) {
                int row  = wn + p*16 + (lane & 7) + ((lane & 16) ? 8 : 0);
                int unit = kc*2 + ((lane >> 3) & 1);
                uint32_t t[4];
                ldsm4(t, bb + SWZ(row*128 + unit*16));
                bfr[p*2][0]   = t[0]; bfr[p*2][1]   = t[1];
                bfr[p*2+1][0] = t[2]; bfr[p*2+1][1] = t[3];
            }
            #pragma unroll
            for (int mi = 0; mi < MI; mi++)
                #pragma unroll
                for (int nj = 0; nj < NJ; nj++)
                    mma16816(d[mi][nj], afr[mi], bfr[nj]);
        }
        __syncthreads();
        if (kb + 2 < NKB) load_tile(kb + 2, kb & 1);
    }

    // ---------------- epilogue ----------------
    #pragma unroll
    for (int mi = 0; mi < MI; mi++) {
        int m0 = bm + wm + mi*16 + (lane >> 2);
        #pragma unroll
        for (int nj = 0; nj < NJ; nj++) {
            int n0 = bn + wn + nj*8 + (lane & 3)*2;
            float b0 = __ldg(bias + n0), b1 = __ldg(bias + n0 + 1);
            #pragma unroll
            for (int h = 0; h < 2; h++) {
                int m = m0 + h*8;
                if (m >= M1) continue;
                float v0 = d[mi][nj][h*2+0] + b0;
                float v1 = d[mi][nj][h*2+1] + b1;
                if (MODE == 0) {
                    v0 = fmaxf(v0, 0.f); v1 = fmaxf(v1, 0.f);
                    __half h0, l0, h1, l1;
                    split_f16(v0, h0, l0); split_f16(v1, h1, l1);
                    __half hh[2] = {h0, h1}, ll[2] = {l0, l1};
                    size_t base = (size_t)m*KA2 + n0;
                    *(uint32_t*)(g_A2 + base)      = *(uint32_t*)hh;
                    *(uint32_t*)(g_A2 + base + K2) = *(uint32_t*)ll;
                } else {
                    float2 o; o.x = v0; o.y = v1;
                    *(float2*)(outp + (size_t)m*N2 + n0) = o;
                }
            }
        }
    }
}

// ================= epilogues =================
__global__ __launch_bounds__(256) void valid_kernel(float* __restrict__ out) {
    int m = blockIdx.x;
    float* row = out + (size_t)m * N2;
    float s = 0.f;
    for (int i = threadIdx.x; i < N2; i += 256) s += row[i];
    __shared__ float red[8];
    #pragma unroll
    for (int o = 16; o; o >>= 1) s += __shfl_xor_sync(0xffffffffu, s, o);
    if ((threadIdx.x & 31) == 0) red[threadIdx.x >> 5] = s;
    __syncthreads();
    if (threadIdx.x == 0) {
        float t = 0.f;
        #pragma unroll
        for (int w = 0; w < 8; w++) t += red[w];
        red[0] = t;
    }
    __syncthreads();
    bool ok = (red[0] != 0.0f);
    if (!ok)
        for (int i = threadIdx.x; i < N2; i += 256) row[i] = 0.0f;
    if (threadIdx.x == 0) g_valid[m] = ok ? 1 : 0;
}

__global__ void finalize_kernel(float* __restrict__ tail) {
    int t = threadIdx.x, b = t >> 5, lane = t & 31;
    int cnt = 0;
    for (int i = lane; i < 100; i += 32) cnt += g_valid[b*100 + i];
    #pragma unroll
    for (int o = 16; o; o >>= 1) cnt += __shfl_xor_sync(0xffffffffu, cnt, o);
    if (lane == 0) tail[b] = (float)(cnt + 1);
}

// ================= launch =================
extern "C" void kernel_launch(void* const* d_in, const int* in_sizes, int n_in,
                              void* d_out, int out_size) {
    const float* voxels     = (const float*)d_in[0];
    const int*   num_points = (const int*)  d_in[1];
    const int*   coors      = (const int*)  d_in[2];
    const float* w_pfn      = (const float*)d_in[3];
    const float* bn_gamma   = (const float*)d_in[4];
    const float* bn_beta    = (const float*)d_in[5];
    const float* bn_mean    = (const float*)d_in[6];
    const float* bn_var     = (const float*)d_in[7];
    const float* conv1_w    = (const float*)d_in[8];
    const float* conv1_b    = (const float*)d_in[9];
    const float* conv2_w    = (const float*)d_in[10];
    const float* conv2_b    = (const float*)d_in[11];
    float* out = (float*)d_out;

    constexpr int SMEM1 = (64*128 + 64*128)  * 2;    // 32768
    constexpr int SMEM2 = (64*128 + 128*128) * 2;    // 49152
    static bool attr_done = false;
    if (!attr_done) {
        cudaFuncSetAttribute(gemm_mma<64, 64,  KA1, 0>, cudaFuncAttributeMaxDynamicSharedMemorySize, SMEM1);
        cudaFuncSetAttribute(gemm_mma<64, 128, KA2, 1>, cudaFuncAttributeMaxDynamicSharedMemorySize, SMEM2);
        attr_done = true;
    }

    prep_w1<<<(N1*K1 + 255)/256, 256>>>(conv1_w);
    prep_w2<<<(N2*K2/4 + 255)/256, 256>>>(conv2_w);

    pfn_kernel<<<MPIL, 128>>>(voxels, num_points, coors, w_pfn,
                              bn_gamma, bn_beta, bn_mean, bn_var);
    prep_a1<<<(M1*(K1/8) + 255)/256, 256>>>();

    gemm_mma<64, 64,  KA1, 0><<<dim3(N1/64,  MPAD/64), 256, SMEM1>>>(conv1_b, nullptr);
    gemm_mma<64, 128, KA2, 1><<<dim3(N2/128, MPAD/64), 256, SMEM2>>>(conv2_b, out);

    valid_kernel<<<M1, 256>>>(out);
    if (out_size >= OUT_MAIN + BATCH)
        finalize_kernel<<<1, 256>>>(out + OUT_MAIN);
}

// round 8
// speedup vs baseline: 4.5692x; 1.3718x over previous
#include <cuda_runtime.h>
#include <cuda_fp16.h>
#include <cstdint>
#include <math.h>

// ---------------- problem constants ----------------
#define BATCH   8
#define GH      40
#define GW      40
#define MPIL    (BATCH*GH*GW)      // 12800 pillars
#define NPTS    32
#define CIN     6
#define CF      256
#define NFEAT   12

#define M1      800
#define MPAD    896                // 14 * 64, padded M for guard-free loads
#define N1      1024
#define K1      2304               // 9 taps * 256
#define N2      4096
#define K2      1024
#define OUT_MAIN (M1*N2)           // 3276800

// ---------------- device scratch ----------------
__device__ float   g_canvas[BATCH*GH*GW*CF];
__device__ __half  g_A1[MPAD*K1];
__device__ __half  g_B1[N1*K1];
__device__ __half  g_A2[MPAD*K2];
__device__ __half  g_B2[N2*K2];
__device__ int     g_valid[M1];

// ================= helpers =================
__device__ __forceinline__ uint32_t smem_to_u32(const void* p) {
    uint32_t a;
    asm("{ .reg .u64 t; cvta.to.shared.u64 t, %1; cvt.u32.u64 %0, t; }" : "=r"(a) : "l"(p));
    return a;
}
#define SWZ(x) ((uint32_t)(x) ^ (((uint32_t)(x) >> 3) & 0x70))

__device__ __forceinline__ void cpa16(uint32_t dst, const void* src) {
    asm volatile("cp.async.cg.shared.global [%0], [%1], 16;"
                 :: "r"(dst), "l"(src) : "memory");
}
#define CP_COMMIT() asm volatile("cp.async.commit_group;" ::: "memory")

__device__ __forceinline__ void ldsm4(uint32_t* r, uint32_t addr) {
    asm volatile("ldmatrix.sync.aligned.m8n8.x4.shared.b16 {%0,%1,%2,%3}, [%4];"
        : "=r"(r[0]), "=r"(r[1]), "=r"(r[2]), "=r"(r[3]) : "r"(addr));
}
__device__ __forceinline__ void mma16816(float* d, const uint32_t* a, const uint32_t* b) {
    asm volatile(
        "mma.sync.aligned.m16n8k16.row.col.f32.f16.f16.f32 "
        "{%0,%1,%2,%3}, {%4,%5,%6,%7}, {%8,%9}, {%0,%1,%2,%3};"
        : "+f"(d[0]), "+f"(d[1]), "+f"(d[2]), "+f"(d[3])
        : "r"(a[0]), "r"(a[1]), "r"(a[2]), "r"(a[3]), "r"(b[0]), "r"(b[1]));
}

// packed fp32x2 (sm_100+ family feature, legal at compute_103)
#define PACK2(out, lo, hi)  asm("mov.b64 %0, {%1, %2};" : "=l"(out) : "f"(lo), "f"(hi))
#define BCAST2(out, v)      asm("mov.b64 %0, {%1, %1};" : "=l"(out) : "f"(v))
#define UNPACK2(lo, hi, in) asm("mov.b64 {%0, %1}, %2;" : "=f"(lo), "=f"(hi) : "l"(in))
#define FMA2(acc, a, b)     asm("fma.rn.f32x2 %0, %1, %2, %0;" : "+l"(acc) : "l"(a), "l"(b))

// ================= prep kernels =================
__global__ void prep_w1(const float* __restrict__ w) {       // w[o][ci][tap] -> Bh[o][k]
    int idx = blockIdx.x*256 + threadIdx.x;
    if (idx >= N1*K1) return;
    int o = idx / K1, k = idx - o*K1;
    int tap = k >> 8, ci = k & 255;
    g_B1[idx] = __float2half_rn(w[(size_t)(o*CF + ci)*9 + tap]);
}

__global__ void prep_w2(const float* __restrict__ w) {       // w[o][k], 4 k per thread
    int t = blockIdx.x*256 + threadIdx.x;
    if (t >= N2*K2/4) return;
    float4 v = *(const float4*)(w + (size_t)t*4);
    __half h[4];
    h[0]=__float2half_rn(v.x); h[1]=__float2half_rn(v.y);
    h[2]=__float2half_rn(v.z); h[3]=__float2half_rn(v.w);
    *(uint2*)(g_B2 + (size_t)t*4) = *(uint2*)h;
}

__global__ void prep_a1() {   // gather conv1 implicit-GEMM A panel, 8 k per thread
    int t = blockIdx.x*256 + threadIdx.x;
    if (t >= M1*(K1/8)) return;
    int m = t / (K1/8);
    int k0 = (t - m*(K1/8)) << 3;          // one tap per thread
    int b = m / 100, p = m - b*100, hp = p / 10, wp = p - hp*10;
    int tap = k0 >> 8, ci = k0 & 255;
    int kh = tap / 3, kw = tap - 3*kh;
    int ih = 4*hp + kh - 1, iw = 4*wp + kw - 1;
    float4 v0 = make_float4(0,0,0,0), v1 = v0;
    if ((unsigned)ih < (unsigned)GH && (unsigned)iw < (unsigned)GW) {
        const float* src = g_canvas + (((size_t)b*GH + ih)*GW + iw)*CF + ci;
        v0 = *(const float4*)src; v1 = *(const float4*)(src + 4);
    }
    __half h[8];
    h[0]=__float2half_rn(v0.x); h[1]=__float2half_rn(v0.y);
    h[2]=__float2half_rn(v0.z); h[3]=__float2half_rn(v0.w);
    h[4]=__float2half_rn(v1.x); h[5]=__float2half_rn(v1.y);
    h[6]=__float2half_rn(v1.z); h[7]=__float2half_rn(v1.w);
    *(uint4*)(g_A1 + (size_t)m*K1 + k0) = *(uint4*)h;
}

// ================= PFN (128 threads, 2 channels each, fma.rn.f32x2) =====
__global__ __launch_bounds__(128) void pfn_kernel(
    const float* __restrict__ voxels, const int* __restrict__ num_points,
    const int* __restrict__ coors,    const float* __restrict__ w,
    const float* __restrict__ bn_gamma, const float* __restrict__ bn_beta,
    const float* __restrict__ bn_mean,  const float* __restrict__ bn_var)
{
    int m = blockIdx.x;
    int f = threadIdx.x;                 // channels f and f+128
    __shared__ float feats[NPTS][NFEAT];
    __shared__ float smean[3];

    int np = num_points[m];
    const float* vox = voxels + (size_t)m * NPTS * CIN;

    float x=0.f, y=0.f, z=0.f, msk=0.f;
    if (f < NPTS) {                      // warp 0 only
        int n = f;
        msk = (n < np) ? 1.0f : 0.0f;
        x = vox[n*CIN+0]; y = vox[n*CIN+1]; z = vox[n*CIN+2];
        float mx=x*msk, my=y*msk, mz=z*msk;
        #pragma unroll
        for (int o = 16; o; o >>= 1) {
            mx += __shfl_xor_sync(0xffffffffu, mx, o);
            my += __shfl_xor_sync(0xffffffffu, my, o);
            mz += __shfl_xor_sync(0xffffffffu, mz, o);
        }
        if (n == 0) {
            float inv = 1.0f / (float)np;
            smean[0]=mx*inv; smean[1]=my*inv; smean[2]=mz*inv;
        }
    }
    __syncthreads();
    if (f < NPTS) {
        int n = f;
        float cx = (float)coors[m*4+3]*0.025f + (0.0125f - 0.5f);
        float cy = (float)coors[m*4+2]*0.025f + (0.0125f - 0.5f);
        float cz = (float)coors[m*4+1]*1.0f + 0.5f;
        feats[n][0]=x*msk;  feats[n][1]=y*msk;  feats[n][2]=z*msk;
        feats[n][3]=vox[n*CIN+3]*msk; feats[n][4]=vox[n*CIN+4]*msk; feats[n][5]=vox[n*CIN+5]*msk;
        feats[n][6]=(x-smean[0])*msk; feats[n][7]=(y-smean[1])*msk; feats[n][8]=(z-smean[2])*msk;
        feats[n][9]=(x-cx)*msk; feats[n][10]=(y-cy)*msk; feats[n][11]=(z-cz)*msk;
    }
    __syncthreads();

    // fold BN: h = s*scale + (beta - mean*scale); pack channel pair (f, f+128)
    int f1 = f + 128;
    float sc0 = bn_gamma[f]  * rsqrtf(bn_var[f]  + 1e-3f);
    float sc1 = bn_gamma[f1] * rsqrtf(bn_var[f1] + 1e-3f);
    float bt0 = bn_beta[f]  - bn_mean[f]  * sc0;
    float bt1 = bn_beta[f1] - bn_mean[f1] * sc1;
    unsigned long long w2[NFEAT], bt2;
    #pragma unroll
    for (int d = 0; d < NFEAT; d++)
        PACK2(w2[d], w[d*CF + f] * sc0, w[d*CF + f1] * sc1);
    PACK2(bt2, bt0, bt1);

    float vmax0 = (np < NPTS) ? fmaxf(bt0, 0.f) : 0.f;
    float vmax1 = (np < NPTS) ? fmaxf(bt1, 0.f) : 0.f;
    #pragma unroll 2
    for (int n = 0; n < np; n++) {
        unsigned long long acc = bt2;
        #pragma unroll
        for (int d = 0; d < NFEAT; d++) {
            unsigned long long f2;
            BCAST2(f2, feats[n][d]);
            FMA2(acc, f2, w2[d]);
        }
        float h0, h1; UNPACK2(h0, h1, acc);
        vmax0 = fmaxf(vmax0, h0);
        vmax1 = fmaxf(vmax1, h1);
    }

    int b = coors[m*4+0], yy = coors[m*4+2], xx = coors[m*4+3];
    size_t px = (((size_t)b*GH + yy)*GW + xx)*CF;
    g_canvas[px + f]  = vmax0;
    g_canvas[px + f1] = vmax1;
}

// ================= mma.sync GEMM (plain fp16 both sides) =================
// D[BM x BN] = A[BM x K] * B^T[K x BN]; fp32 accum.
// 8 warps as 2(M) x 4(N). MODE 0: conv1 -> relu(+bias), write g_A2 fp16.
// MODE 1: conv2 -> +bias, write outp fp32 rows.
template<int BM, int BN, int K, int MODE>
__global__ __launch_bounds__(256) void gemm_mma(const float* __restrict__ bias,
                                                float* __restrict__ outp)
{
    extern __shared__ __align__(1024) char smem[];
    constexpr int NKB = K / 64;
    constexpr int ASZ = BM*128;
    constexpr int BSZ = BN*128;
    constexpr int MW = 2;
    constexpr int WMS = BM/MW;               // 32
    constexpr int MI  = WMS/16;              // 2
    constexpr int WNS = BN/4;
    constexpr int NJ  = WNS/8;               // 2 (BN=64) / 4 (BN=128)

    const uint32_t sbase = smem_to_u32(smem);
    const int tid  = threadIdx.x;
    const int lane = tid & 31, wid = tid >> 5;
    const int warpM = wid & (MW-1), warpN = wid >> 1;
    const int bn = blockIdx.x * BN, bm = blockIdx.y * BM;
    const int wm = warpM*WMS, wn = warpN*WNS;

    const __half* __restrict__ A  = (MODE == 0) ? g_A1 : g_A2;
    const __half* __restrict__ Bm = (MODE == 0) ? g_B1 : g_B2;

    float d[MI][NJ][4];
    #pragma unroll
    for (int mi=0;mi<MI;mi++)
        #pragma unroll
        for (int nj=0;nj<NJ;nj++)
            #pragma unroll
            for (int c=0;c<4;c++) d[mi][nj][c] = 0.f;

    auto load_tile = [&](int kb, int buf) {
        const uint32_t ab = sbase + (uint32_t)buf*(ASZ+BSZ);
        const uint32_t bb = ab + ASZ;
        int koff = kb*64;
        #pragma unroll
        for (int i = 0; i < BM*8/256; i++) {
            int c = tid + i*256;
            int r = c >> 3, u = c & 7;
            cpa16(ab + SWZ(r*128 + u*16), A + (size_t)(bm + r)*K + koff + u*8);
        }
        #pragma unroll
        for (int i = 0; i < BN*8/256; i++) {
            int c = tid + i*256;
            int r = c >> 3, u = c & 7;
            cpa16(bb + SWZ(r*128 + u*16), Bm + (size_t)(bn + r)*K + koff + u*8);
        }
        CP_COMMIT();
    };

    load_tile(0, 0);
    load_tile(1, 1);

    for (int kb = 0; kb < NKB; kb++) {
        if (kb + 1 < NKB) asm volatile("cp.async.wait_group 1;" ::: "memory");
        else              asm volatile("cp.async.wait_group 0;" ::: "memory");
        __syncthreads();

        const uint32_t ab = sbase + (uint32_t)(kb & 1)*(ASZ+BSZ);
        const uint32_t bb = ab + ASZ;
        #pragma unroll
        for (int kc = 0; kc < 4; kc++) {
            uint32_t afr[MI][4];
            #pragma unroll
            for (int mi = 0; mi < MI; mi++) {
                int row  = wm + mi*16 + (lane & 15);
                int unit = kc*2 + (lane >> 4);
                ldsm4(afr[mi], ab + SWZ(row*128 + unit*16));
            }
            uint32_t bfr[NJ][2];
            #pragma unroll
            for (int p = 0; p < NJ/2; p++) {
                int row  = wn + p*16 + (lane & 7) + ((lane & 16) ? 8 : 0);
                int unit = kc*2 + ((lane >> 3) & 1);
                uint32_t t[4];
                ldsm4(t, bb + SWZ(row*128 + unit*16));
                bfr[p*2][0]   = t[0]; bfr[p*2][1]   = t[1];
                bfr[p*2+1][0] = t[2]; bfr[p*2+1][1] = t[3];
            }
            #pragma unroll
            for (int mi = 0; mi < MI; mi++)
                #pragma unroll
                for (int nj = 0; nj < NJ; nj++)
                    mma16816(d[mi][nj], afr[mi], bfr[nj]);
        }
        __syncthreads();
        if (kb + 2 < NKB) load_tile(kb + 2, kb & 1);
    }

    // ---------------- epilogue ----------------
    #pragma unroll
    for (int mi = 0; mi < MI; mi++) {
        int m0 = bm + wm + mi*16 + (lane >> 2);
        #pragma unroll
        for (int nj = 0; nj < NJ; nj++) {
            int n0 = bn + wn + nj*8 + (lane & 3)*2;
            float b0 = __ldg(bias + n0), b1 = __ldg(bias + n0 + 1);
            #pragma unroll
            for (int h = 0; h < 2; h++) {
                int m = m0 + h*8;
                if (m >= M1) continue;
                float v0 = d[mi][nj][h*2+0] + b0;
                float v1 = d[mi][nj][h*2+1] + b1;
                if (MODE == 0) {
                    __half hh[2];
                    hh[0] = __float2half_rn(fmaxf(v0, 0.f));
                    hh[1] = __float2half_rn(fmaxf(v1, 0.f));
                    *(uint32_t*)(g_A2 + (size_t)m*K2 + n0) = *(uint32_t*)hh;
                } else {
                    float2 o; o.x = v0; o.y = v1;
                    *(float2*)(outp + (size_t)m*N2 + n0) = o;
                }
            }
        }
    }
}

// ================= epilogues =================
__global__ __launch_bounds__(256) void valid_kernel(float* __restrict__ out) {
    int m = blockIdx.x;
    float* row = out + (size_t)m * N2;
    float s = 0.f;
    for (int i = threadIdx.x; i < N2; i += 256) s += row[i];
    __shared__ float red[8];
    #pragma unroll
    for (int o = 16; o; o >>= 1) s += __shfl_xor_sync(0xffffffffu, s, o);
    if ((threadIdx.x & 31) == 0) red[threadIdx.x >> 5] = s;
    __syncthreads();
    if (threadIdx.x == 0) {
        float t = 0.f;
        #pragma unroll
        for (int w = 0; w < 8; w++) t += red[w];
        red[0] = t;
    }
    __syncthreads();
    bool ok = (red[0] != 0.0f);
    if (!ok)
        for (int i = threadIdx.x; i < N2; i += 256) row[i] = 0.0f;
    if (threadIdx.x == 0) g_valid[m] = ok ? 1 : 0;
}

__global__ void finalize_kernel(float* __restrict__ tail) {
    int t = threadIdx.x, b = t >> 5, lane = t & 31;
    int cnt = 0;
    for (int i = lane; i < 100; i += 32) cnt += g_valid[b*100 + i];
    #pragma unroll
    for (int o = 16; o; o >>= 1) cnt += __shfl_xor_sync(0xffffffffu, cnt, o);
    if (lane == 0) tail[b] = (float)(cnt + 1);
}

// ================= launch =================
extern "C" void kernel_launch(void* const* d_in, const int* in_sizes, int n_in,
                              void* d_out, int out_size) {
    const float* voxels     = (const float*)d_in[0];
    const int*   num_points = (const int*)  d_in[1];
    const int*   coors      = (const int*)  d_in[2];
    const float* w_pfn      = (const float*)d_in[3];
    const float* bn_gamma   = (const float*)d_in[4];
    const float* bn_beta    = (const float*)d_in[5];
    const float* bn_mean    = (const float*)d_in[6];
    const float* bn_var     = (const float*)d_in[7];
    const float* conv1_w    = (const float*)d_in[8];
    const float* conv1_b    = (const float*)d_in[9];
    const float* conv2_w    = (const float*)d_in[10];
    const float* conv2_b    = (const float*)d_in[11];
    float* out = (float*)d_out;

    constexpr int SMEM1 = (64*128 + 64*128)  * 2;    // 32768
    constexpr int SMEM2 = (64*128 + 128*128) * 2;    // 49152
    static bool attr_done = false;
    if (!attr_done) {
        cudaFuncSetAttribute(gemm_mma<64, 64,  K1, 0>, cudaFuncAttributeMaxDynamicSharedMemorySize, SMEM1);
        cudaFuncSetAttribute(gemm_mma<64, 128, K2, 1>, cudaFuncAttributeMaxDynamicSharedMemorySize, SMEM2);
        attr_done = true;
    }

    prep_w1<<<(N1*K1 + 255)/256, 256>>>(conv1_w);
    prep_w2<<<(N2*K2/4 + 255)/256, 256>>>(conv2_w);

    pfn_kernel<<<MPIL, 128>>>(voxels, num_points, coors, w_pfn,
                              bn_gamma, bn_beta, bn_mean, bn_var);
    prep_a1<<<(M1*(K1/8) + 255)/256, 256>>>();

    gemm_mma<64, 64,  K1, 0><<<dim3(N1/64,  MPAD/64), 256, SMEM1>>>(conv1_b, nullptr);
    gemm_mma<64, 128, K2, 1><<<dim3(N2/128, MPAD/64), 256, SMEM2>>>(conv2_b, out);

    valid_kernel<<<M1, 256>>>(out);
    if (out_size >= OUT_MAIN + BATCH)
        finalize_kernel<<<1, 256>>>(out + OUT_MAIN);
}

// round 9
// speedup vs baseline: 4.7188x; 1.0327x over previous
#include <cuda_runtime.h>
#include <cuda_fp16.h>
#include <cstdint>
#include <math.h>

// ---------------- problem constants ----------------
#define BATCH   8
#define GH      40
#define GW      40
#define MPIL    (BATCH*GH*GW)      // 12800 pillars
#define NPTS    32
#define CIN     6
#define CF      256
#define NFEAT   12

#define M1      800
#define MPAD    896                // 14 * 64, padded M for guard-free loads
#define N1      1024
#define K1      2304               // 9 taps * 256
#define N2      4096
#define K2      1024
#define OUT_MAIN (M1*N2)           // 3276800

// ---------------- device scratch ----------------
__device__ __half  g_canvas_h[MPIL*CF];   // NHWC fp16 canvas
__device__ __half  g_B1[N1*K1];
__device__ __half  g_A2[MPAD*K2];
__device__ __half  g_B2[N2*K2];
__device__ float   g_rowsum[M1];
__device__ int     g_valid[M1];

// ================= helpers =================
__device__ __forceinline__ uint32_t smem_to_u32(const void* p) {
    uint32_t a;
    asm("{ .reg .u64 t; cvta.to.shared.u64 t, %1; cvt.u32.u64 %0, t; }" : "=r"(a) : "l"(p));
    return a;
}
#define SWZ(x) ((uint32_t)(x) ^ (((uint32_t)(x) >> 3) & 0x70))

__device__ __forceinline__ void cpa16(uint32_t dst, const void* src) {
    asm volatile("cp.async.cg.shared.global [%0], [%1], 16;"
                 :: "r"(dst), "l"(src) : "memory");
}
__device__ __forceinline__ void cpa16p(uint32_t dst, const void* src, uint32_t srcsize) {
    asm volatile("cp.async.cg.shared.global [%0], [%1], 16, %2;"
                 :: "r"(dst), "l"(src), "r"(srcsize) : "memory");
}
#define CP_COMMIT() asm volatile("cp.async.commit_group;" ::: "memory")

__device__ __forceinline__ void ldsm4(uint32_t* r, uint32_t addr) {
    asm volatile("ldmatrix.sync.aligned.m8n8.x4.shared.b16 {%0,%1,%2,%3}, [%4];"
        : "=r"(r[0]), "=r"(r[1]), "=r"(r[2]), "=r"(r[3]) : "r"(addr));
}
__device__ __forceinline__ void mma16816(float* d, const uint32_t* a, const uint32_t* b) {
    asm volatile(
        "mma.sync.aligned.m16n8k16.row.col.f32.f16.f16.f32 "
        "{%0,%1,%2,%3}, {%4,%5,%6,%7}, {%8,%9}, {%0,%1,%2,%3};"
        : "+f"(d[0]), "+f"(d[1]), "+f"(d[2]), "+f"(d[3])
        : "r"(a[0]), "r"(a[1]), "r"(a[2]), "r"(a[3]), "r"(b[0]), "r"(b[1]));
}

// packed fp32x2 (sm_100+ family feature, legal at compute_103)
#define PACK2(out, lo, hi)  asm("mov.b64 %0, {%1, %2};" : "=l"(out) : "f"(lo), "f"(hi))
#define BCAST2(out, v)      asm("mov.b64 %0, {%1, %1};" : "=l"(out) : "f"(v))
#define UNPACK2(lo, hi, in) asm("mov.b64 {%0, %1}, %2;" : "=f"(lo), "=f"(hi) : "l"(in))
#define FMA2(acc, a, b)     asm("fma.rn.f32x2 %0, %1, %2, %0;" : "+l"(acc) : "l"(a), "l"(b))

// ================= fused weight prep (+ rowsum clear) =================
__global__ void prep_w(const float* __restrict__ w1, const float* __restrict__ w2) {
    int idx = blockIdx.x*256 + threadIdx.x;
    if (idx < M1) g_rowsum[idx] = 0.f;                 // clear for this replay
    if (idx < N1*K1) {                                 // w1[o][ci][tap] -> B1[o][k]
        int o = idx / K1, k = idx - o*K1;
        int tap = k >> 8, ci = k & 255;
        g_B1[idx] = __float2half_rn(w1[(size_t)(o*CF + ci)*9 + tap]);
    }
    int t = idx - N1*K1;
    if (t >= 0 && t < N2*K2/4) {                       // w2[o][k], 4 per thread
        float4 v = *(const float4*)(w2 + (size_t)t*4);
        __half h[4];
        h[0]=__float2half_rn(v.x); h[1]=__float2half_rn(v.y);
        h[2]=__float2half_rn(v.z); h[3]=__float2half_rn(v.w);
        *(uint2*)(g_B2 + (size_t)t*4) = *(uint2*)h;
    }
}

// ================= PFN (128 threads, 2 channels each, fma.rn.f32x2) =====
__global__ __launch_bounds__(128) void pfn_kernel(
    const float* __restrict__ voxels, const int* __restrict__ num_points,
    const int* __restrict__ coors,    const float* __restrict__ w,
    const float* __restrict__ bn_gamma, const float* __restrict__ bn_beta,
    const float* __restrict__ bn_mean,  const float* __restrict__ bn_var)
{
    int m = blockIdx.x;
    int f = threadIdx.x;                 // channels f and f+128
    __shared__ float feats[NPTS][NFEAT];
    __shared__ float smean[3];

    int np = num_points[m];
    const float* vox = voxels + (size_t)m * NPTS * CIN;

    float x=0.f, y=0.f, z=0.f, msk=0.f;
    if (f < NPTS) {                      // warp 0 only
        int n = f;
        msk = (n < np) ? 1.0f : 0.0f;
        x = vox[n*CIN+0]; y = vox[n*CIN+1]; z = vox[n*CIN+2];
        float mx=x*msk, my=y*msk, mz=z*msk;
        #pragma unroll
        for (int o = 16; o; o >>= 1) {
            mx += __shfl_xor_sync(0xffffffffu, mx, o);
            my += __shfl_xor_sync(0xffffffffu, my, o);
            mz += __shfl_xor_sync(0xffffffffu, mz, o);
        }
        if (n == 0) {
            float inv = 1.0f / (float)np;
            smean[0]=mx*inv; smean[1]=my*inv; smean[2]=mz*inv;
        }
    }
    __syncthreads();
    if (f < NPTS) {
        int n = f;
        float cx = (float)coors[m*4+3]*0.025f + (0.0125f - 0.5f);
        float cy = (float)coors[m*4+2]*0.025f + (0.0125f - 0.5f);
        float cz = (float)coors[m*4+1]*1.0f + 0.5f;
        feats[n][0]=x*msk;  feats[n][1]=y*msk;  feats[n][2]=z*msk;
        feats[n][3]=vox[n*CIN+3]*msk; feats[n][4]=vox[n*CIN+4]*msk; feats[n][5]=vox[n*CIN+5]*msk;
        feats[n][6]=(x-smean[0])*msk; feats[n][7]=(y-smean[1])*msk; feats[n][8]=(z-smean[2])*msk;
        feats[n][9]=(x-cx)*msk; feats[n][10]=(y-cy)*msk; feats[n][11]=(z-cz)*msk;
    }
    __syncthreads();

    // fold BN: h = s*scale + (beta - mean*scale); pack channel pair (f, f+128)
    int f1 = f + 128;
    float sc0 = bn_gamma[f]  * rsqrtf(bn_var[f]  + 1e-3f);
    float sc1 = bn_gamma[f1] * rsqrtf(bn_var[f1] + 1e-3f);
    float bt0 = bn_beta[f]  - bn_mean[f]  * sc0;
    float bt1 = bn_beta[f1] - bn_mean[f1] * sc1;
    unsigned long long w2[NFEAT], bt2;
    #pragma unroll
    for (int d = 0; d < NFEAT; d++)
        PACK2(w2[d], w[d*CF + f] * sc0, w[d*CF + f1] * sc1);
    PACK2(bt2, bt0, bt1);

    float vmax0 = (np < NPTS) ? fmaxf(bt0, 0.f) : 0.f;
    float vmax1 = (np < NPTS) ? fmaxf(bt1, 0.f) : 0.f;
    #pragma unroll 2
    for (int n = 0; n < np; n++) {
        unsigned long long acc = bt2;
        #pragma unroll
        for (int d = 0; d < NFEAT; d++) {
            unsigned long long f2;
            BCAST2(f2, feats[n][d]);
            FMA2(acc, f2, w2[d]);
        }
        float h0, h1; UNPACK2(h0, h1, acc);
        vmax0 = fmaxf(vmax0, h0);
        vmax1 = fmaxf(vmax1, h1);
    }

    int b = coors[m*4+0], yy = coors[m*4+2], xx = coors[m*4+3];
    size_t px = (((size_t)b*GH + yy)*GW + xx)*CF;
    g_canvas_h[px + f]  = __float2half_rn(vmax0);
    g_canvas_h[px + f1] = __float2half_rn(vmax1);
}

// ================= mma.sync GEMM (plain fp16 both sides) =================
// MODE 0: conv1 implicit GEMM — A gathered from fp16 canvas (zero-fill halo),
//         epilogue relu(+bias) -> g_A2 fp16.
// MODE 1: conv2 — A = g_A2, epilogue +bias -> outp fp32 + rowsum atomics.
template<int BM, int BN, int K, int MODE>
__global__ __launch_bounds__(256) void gemm_mma(const float* __restrict__ bias,
                                                float* __restrict__ outp)
{
    extern __shared__ __align__(1024) char smem[];
    constexpr int NKB = K / 64;
    constexpr int ASZ = BM*128;
    constexpr int BSZ = BN*128;
    constexpr int MW = 2;
    constexpr int WMS = BM/MW;               // 32
    constexpr int MI  = WMS/16;              // 2
    constexpr int WNS = BN/4;
    constexpr int NJ  = WNS/8;               // 2 (BN=64) / 4 (BN=128)
    constexpr int AIT = BM*8/256;            // 2

    const uint32_t sbase = smem_to_u32(smem);
    const int tid  = threadIdx.x;
    const int lane = tid & 31, wid = tid >> 5;
    const int warpM = wid & (MW-1), warpN = wid >> 1;
    const int bn = blockIdx.x * BN, bm = blockIdx.y * BM;
    const int wm = warpM*WMS, wn = warpN*WNS;

    const __half* __restrict__ Bm = (MODE == 0) ? g_B1 : g_B2;

    // hoisted per-thread A-loader state
    uint32_t dstA[AIT];
    int aoff[AIT];          // MODE1: element offset; MODE0: b*409600 + u*8
    int ihb[AIT], iwb[AIT];
    bool mok[AIT];
    #pragma unroll
    for (int i = 0; i < AIT; i++) {
        int c = tid + i*256;
        int r = c >> 3, u = c & 7;
        int m = bm + r;
        dstA[i] = SWZ(r*128 + u*16);
        mok[i] = m < M1;
        if (MODE == 0) {
            int mc = mok[i] ? m : 0;
            int b = mc / 100, p = mc - b*100;
            int hp = p / 10, wp = p - hp*10;
            ihb[i] = 4*hp - 1; iwb[i] = 4*wp - 1;
            aoff[i] = b*(GH*GW*CF) + u*8;
        } else {
            aoff[i] = (mok[i] ? m : 0)*K + u*8;
        }
    }

    float d[MI][NJ][4];
    #pragma unroll
    for (int mi=0;mi<MI;mi++)
        #pragma unroll
        for (int nj=0;nj<NJ;nj++)
            #pragma unroll
            for (int c=0;c<4;c++) d[mi][nj][c] = 0.f;

    auto load_tile = [&](int kb, int buf) {
        const uint32_t ab = sbase + (uint32_t)buf*(ASZ+BSZ);
        const uint32_t bb = ab + ASZ;
        int koff = kb*64;
        if (MODE == 0) {
            int tap = kb >> 2, ci0 = (kb & 3) << 6;
            int kh = tap / 3, kw = tap - 3*kh;
            #pragma unroll
            for (int i = 0; i < AIT; i++) {
                int ih = ihb[i] + kh, iw = iwb[i] + kw;
                bool ok = mok[i] && (unsigned)ih < (unsigned)GH && (unsigned)iw < (unsigned)GW;
                const __half* src = g_canvas_h +
                    (ok ? (aoff[i] + (ih*GW + iw)*CF + ci0) : 0);
                cpa16p(ab + dstA[i], src, ok ? 16u : 0u);
            }
        } else {
            #pragma unroll
            for (int i = 0; i < AIT; i++)
                cpa16(ab + dstA[i], g_A2 + (size_t)aoff[i] + koff);
        }
        #pragma unroll
        for (int i = 0; i < BN*8/256; i++) {
            int c = tid + i*256;
            int r = c >> 3, u = c & 7;
            cpa16(bb + SWZ(r*128 + u*16), Bm + (size_t)(bn + r)*K + koff + u*8);
        }
        CP_COMMIT();
    };

    load_tile(0, 0);
    load_tile(1, 1);

    for (int kb = 0; kb < NKB; kb++) {
        if (kb + 1 < NKB) asm volatile("cp.async.wait_group 1;" ::: "memory");
        else              asm volatile("cp.async.wait_group 0;" ::: "memory");
        __syncthreads();

        const uint32_t ab = sbase + (uint32_t)(kb & 1)*(ASZ+BSZ);
        const uint32_t bb = ab + ASZ;
        #pragma unroll
        for (int kc = 0; kc < 4; kc++) {
            uint32_t afr[MI][4];
            #pragma unroll
            for (int mi = 0; mi < MI; mi++) {
                int row  = wm + mi*16 + (lane & 15);
                int unit = kc*2 + (lane >> 4);
                ldsm4(afr[mi], ab + SWZ(row*128 + unit*16));
            }
            uint32_t bfr[NJ][2];
            #pragma unroll
            for (int p = 0; p < NJ/2; p++) {
                int row  = wn + p*16 + (lane & 7) + ((lane & 16) ? 8 : 0);
                int unit = kc*2 + ((lane >> 3) & 1);
                uint32_t t[4];
                ldsm4(t, bb + SWZ(row*128 + unit*16));
                bfr[p*2][0]   = t[0]; bfr[p*2][1]   = t[1];
                bfr[p*2+1][0] = t[2]; bfr[p*2+1][1] = t[3];
            }
            #pragma unroll
            for (int mi = 0; mi < MI; mi++)
                #pragma unroll
                for (int nj = 0; nj < NJ; nj++)
                    mma16816(d[mi][nj], afr[mi], bfr[nj]);
        }
        __syncthreads();
        if (kb + 2 < NKB) load_tile(kb + 2, kb & 1);
    }

    // ---------------- epilogue ----------------
    #pragma unroll
    for (int mi = 0; mi < MI; mi++) {
        int m0 = bm + wm + mi*16 + (lane >> 2);
        #pragma unroll
        for (int h = 0; h < 2; h++) {
            int m = m0 + h*8;
            bool ok = m < M1;
            float rsum = 0.f;
            #pragma unroll
            for (int nj = 0; nj < NJ; nj++) {
                int n0 = bn + wn + nj*8 + (lane & 3)*2;
                float v0 = d[mi][nj][h*2+0] + __ldg(bias + n0);
                float v1 = d[mi][nj][h*2+1] + __ldg(bias + n0 + 1);
                if (MODE == 0) {
                    if (ok) {
                        __half hh[2];
                        hh[0] = __float2half_rn(fmaxf(v0, 0.f));
                        hh[1] = __float2half_rn(fmaxf(v1, 0.f));
                        *(uint32_t*)(g_A2 + (size_t)m*K2 + n0) = *(uint32_t*)hh;
                    }
                } else {
                    rsum += v0 + v1;
                    if (ok) {
                        float2 o; o.x = v0; o.y = v1;
                        *(float2*)(outp + (size_t)m*N2 + n0) = o;
                    }
                }
            }
            if (MODE == 1) {
                rsum += __shfl_xor_sync(0xffffffffu, rsum, 1);
                rsum += __shfl_xor_sync(0xffffffffu, rsum, 2);
                if ((lane & 3) == 0 && ok)
                    atomicAdd(&g_rowsum[m], rsum);
            }
        }
    }
}

// ================= epilogues =================
__global__ __launch_bounds__(256) void fixup_kernel(float* __restrict__ out) {
    int m = blockIdx.x;
    bool ok = (g_rowsum[m] != 0.0f);
    if (!ok) {
        float* row = out + (size_t)m * N2;
        for (int i = threadIdx.x; i < N2; i += 256) row[i] = 0.0f;
    }
    if (threadIdx.x == 0) g_valid[m] = ok ? 1 : 0;
}

__global__ void finalize_kernel(float* __restrict__ tail) {
    int t = threadIdx.x, b = t >> 5, lane = t & 31;
    int cnt = 0;
    for (int i = lane; i < 100; i += 32) cnt += g_valid[b*100 + i];
    #pragma unroll
    for (int o = 16; o; o >>= 1) cnt += __shfl_xor_sync(0xffffffffu, cnt, o);
    if (lane == 0) tail[b] = (float)(cnt + 1);
}

// ================= launch =================
extern "C" void kernel_launch(void* const* d_in, const int* in_sizes, int n_in,
                              void* d_out, int out_size) {
    const float* voxels     = (const float*)d_in[0];
    const int*   num_points = (const int*)  d_in[1];
    const int*   coors      = (const int*)  d_in[2];
    const float* w_pfn      = (const float*)d_in[3];
    const float* bn_gamma   = (const float*)d_in[4];
    const float* bn_beta    = (const float*)d_in[5];
    const float* bn_mean    = (const float*)d_in[6];
    const float* bn_var     = (const float*)d_in[7];
    const float* conv1_w    = (const float*)d_in[8];
    const float* conv1_b    = (const float*)d_in[9];
    const float* conv2_w    = (const float*)d_in[10];
    const float* conv2_b    = (const float*)d_in[11];
    float* out = (float*)d_out;

    constexpr int SMEM1 = (64*128 + 64*128)  * 2;    // 32768
    constexpr int SMEM2 = (64*128 + 128*128) * 2;    // 49152
    static bool attr_done = false;
    if (!attr_done) {
        cudaFuncSetAttribute(gemm_mma<64, 64,  K1, 0>, cudaFuncAttributeMaxDynamicSharedMemorySize, SMEM1);
        cudaFuncSetAttribute(gemm_mma<64, 128, K2, 1>, cudaFuncAttributeMaxDynamicSharedMemorySize, SMEM2);
        attr_done = true;
    }

    constexpr int PW_TOT = N1*K1 + N2*K2/4;          // 3407872
    prep_w<<<(PW_TOT + 255)/256, 256>>>(conv1_w, conv2_w);

    pfn_kernel<<<MPIL, 128>>>(voxels, num_points, coors, w_pfn,
                              bn_gamma, bn_beta, bn_mean, bn_var);

    gemm_mma<64, 64,  K1, 0><<<dim3(N1/64,  MPAD/64), 256, SMEM1>>>(conv1_b, nullptr);
    gemm_mma<64, 128, K2, 1><<<dim3(N2/128, MPAD/64), 256, SMEM2>>>(conv2_b, out);

    fixup_kernel<<<M1, 256>>>(out);
    if (out_size >= OUT_MAIN + BATCH)
        finalize_kernel<<<1, 256>>>(out + OUT_MAIN);
}

// round 10
// speedup vs baseline: 4.7331x; 1.0030x over previous
#include <cuda_runtime.h>
#include <cuda_fp16.h>
#include <cstdint>
#include <math.h>

// ---------------- problem constants ----------------
#define BATCH   8
#define GH      40
#define GW      40
#define MPIL    (BATCH*GH*GW)      // 12800 pillars
#define NPTS    32
#define CIN     6
#define CF      256
#define NFEAT   12

#define M1      800
#define MPAD    896                // 14 * 64, padded M for guard-free loads
#define N1      1024
#define K1      2304               // 9 taps * 256
#define N2      4096
#define K2      1024
#define OUT_MAIN (M1*N2)           // 3276800

// ---------------- device scratch ----------------
__device__ __half  g_canvas_h[MPIL*CF];   // NHWC fp16 canvas
__device__ __half  g_B1[N1*K1];
__device__ __half  g_A2[MPAD*K2];
__device__ __half  g_B2[N2*K2];
__device__ float   g_rowsum[M1];
__device__ int     g_valid[M1];

// ================= helpers =================
__device__ __forceinline__ uint32_t smem_to_u32(const void* p) {
    uint32_t a;
    asm("{ .reg .u64 t; cvta.to.shared.u64 t, %1; cvt.u32.u64 %0, t; }" : "=r"(a) : "l"(p));
    return a;
}
#define SWZ(x) ((uint32_t)(x) ^ (((uint32_t)(x) >> 3) & 0x70))

__device__ __forceinline__ void cpa16(uint32_t dst, const void* src) {
    asm volatile("cp.async.cg.shared.global [%0], [%1], 16;"
                 :: "r"(dst), "l"(src) : "memory");
}
__device__ __forceinline__ void cpa16p(uint32_t dst, const void* src, uint32_t srcsize) {
    asm volatile("cp.async.cg.shared.global [%0], [%1], 16, %2;"
                 :: "r"(dst), "l"(src), "r"(srcsize) : "memory");
}
#define CP_COMMIT() asm volatile("cp.async.commit_group;" ::: "memory")

__device__ __forceinline__ void ldsm4(uint32_t* r, uint32_t addr) {
    asm volatile("ldmatrix.sync.aligned.m8n8.x4.shared.b16 {%0,%1,%2,%3}, [%4];"
        : "=r"(r[0]), "=r"(r[1]), "=r"(r[2]), "=r"(r[3]) : "r"(addr));
}
__device__ __forceinline__ void mma16816(float* d, const uint32_t* a, const uint32_t* b) {
    asm volatile(
        "mma.sync.aligned.m16n8k16.row.col.f32.f16.f16.f32 "
        "{%0,%1,%2,%3}, {%4,%5,%6,%7}, {%8,%9}, {%0,%1,%2,%3};"
        : "+f"(d[0]), "+f"(d[1]), "+f"(d[2]), "+f"(d[3])
        : "r"(a[0]), "r"(a[1]), "r"(a[2]), "r"(a[3]), "r"(b[0]), "r"(b[1]));
}

// packed fp32x2 (sm_100+ family feature, legal at compute_103)
#define PACK2(out, lo, hi)  asm("mov.b64 %0, {%1, %2};" : "=l"(out) : "f"(lo), "f"(hi))
#define BCAST2(out, v)      asm("mov.b64 %0, {%1, %1};" : "=l"(out) : "f"(v))
#define UNPACK2(lo, hi, in) asm("mov.b64 {%0, %1}, %2;" : "=f"(lo), "=f"(hi) : "l"(in))
#define FMA2(acc, a, b)     asm("fma.rn.f32x2 %0, %1, %2, %0;" : "+l"(acc) : "l"(a), "l"(b))

// ================= fused weight prep (+ rowsum clear) =================
// blocks [0,1024): w1 transpose via SMEM (coalesced both sides)
// blocks [1024, 1024+4096): w2 convert, 4 floats/thread; first 4 also clear rowsum
__global__ __launch_bounds__(256) void prep_w(const float* __restrict__ w1,
                                              const float* __restrict__ w2) {
    int blk = blockIdx.x;
    if (blk < N1) {
        __shared__ float sw[K1];
        const float* src = w1 + (size_t)blk*K1;
        #pragma unroll
        for (int i = threadIdx.x; i < K1; i += 256) sw[i] = src[i];
        __syncthreads();
        #pragma unroll
        for (int i = threadIdx.x; i < K1; i += 256) {
            int tap = i >> 8, ci = i & 255;
            g_B1[(size_t)blk*K1 + i] = __float2half_rn(sw[ci*9 + tap]);
        }
    } else {
        int rb = blk - N1;
        if (rb < 4) {
            int i = rb*256 + threadIdx.x;
            if (i < M1) g_rowsum[i] = 0.f;
        }
        int t = rb*256 + threadIdx.x;          // 4 floats each
        if (t < N2*K2/4) {
            float4 v = *(const float4*)(w2 + (size_t)t*4);
            __half h[4];
            h[0]=__float2half_rn(v.x); h[1]=__float2half_rn(v.y);
            h[2]=__float2half_rn(v.z); h[3]=__float2half_rn(v.w);
            *(uint2*)(g_B2 + (size_t)t*4) = *(uint2*)h;
        }
    }
}

// ================= PFN: 2 pillars per 256-thread block =================
__global__ __launch_bounds__(256) void pfn_kernel(
    const float* __restrict__ voxels, const int* __restrict__ num_points,
    const int* __restrict__ coors,    const float* __restrict__ w,
    const float* __restrict__ bn_gamma, const float* __restrict__ bn_beta,
    const float* __restrict__ bn_mean,  const float* __restrict__ bn_var)
{
    int sub = threadIdx.x >> 7;          // 0/1: which pillar
    int f   = threadIdx.x & 127;         // channels f and f+128
    int m   = blockIdx.x*2 + sub;
    __shared__ float feats[2][NPTS][NFEAT];
    __shared__ float smean[2][3];

    int np = num_points[m];
    const float* vox = voxels + (size_t)m * NPTS * CIN;

    float x=0.f, y=0.f, z=0.f, msk=0.f;
    if (f < NPTS) {                      // warps 0 and 4
        int n = f;
        msk = (n < np) ? 1.0f : 0.0f;
        x = vox[n*CIN+0]; y = vox[n*CIN+1]; z = vox[n*CIN+2];
        float mx=x*msk, my=y*msk, mz=z*msk;
        #pragma unroll
        for (int o = 16; o; o >>= 1) {
            mx += __shfl_xor_sync(0xffffffffu, mx, o);
            my += __shfl_xor_sync(0xffffffffu, my, o);
            mz += __shfl_xor_sync(0xffffffffu, mz, o);
        }
        if (n == 0) {
            float inv = 1.0f / (float)np;
            smean[sub][0]=mx*inv; smean[sub][1]=my*inv; smean[sub][2]=mz*inv;
        }
    }
    __syncthreads();
    if (f < NPTS) {
        int n = f;
        float cx = (float)coors[m*4+3]*0.025f + (0.0125f - 0.5f);
        float cy = (float)coors[m*4+2]*0.025f + (0.0125f - 0.5f);
        float cz = (float)coors[m*4+1]*1.0f + 0.5f;
        feats[sub][n][0]=x*msk;  feats[sub][n][1]=y*msk;  feats[sub][n][2]=z*msk;
        feats[sub][n][3]=vox[n*CIN+3]*msk; feats[sub][n][4]=vox[n*CIN+4]*msk; feats[sub][n][5]=vox[n*CIN+5]*msk;
        feats[sub][n][6]=(x-smean[sub][0])*msk; feats[sub][n][7]=(y-smean[sub][1])*msk; feats[sub][n][8]=(z-smean[sub][2])*msk;
        feats[sub][n][9]=(x-cx)*msk; feats[sub][n][10]=(y-cy)*msk; feats[sub][n][11]=(z-cz)*msk;
    }
    __syncthreads();

    // fold BN: h = s*scale + (beta - mean*scale); pack channel pair (f, f+128)
    int f1 = f + 128;
    float sc0 = bn_gamma[f]  * rsqrtf(bn_var[f]  + 1e-3f);
    float sc1 = bn_gamma[f1] * rsqrtf(bn_var[f1] + 1e-3f);
    float bt0 = bn_beta[f]  - bn_mean[f]  * sc0;
    float bt1 = bn_beta[f1] - bn_mean[f1] * sc1;
    unsigned long long w2v[NFEAT], bt2;
    #pragma unroll
    for (int d = 0; d < NFEAT; d++)
        PACK2(w2v[d], w[d*CF + f] * sc0, w[d*CF + f1] * sc1);
    PACK2(bt2, bt0, bt1);

    float vmax0 = (np < NPTS) ? fmaxf(bt0, 0.f) : 0.f;
    float vmax1 = (np < NPTS) ? fmaxf(bt1, 0.f) : 0.f;
    #pragma unroll 2
    for (int n = 0; n < np; n++) {
        unsigned long long acc = bt2;
        #pragma unroll
        for (int d = 0; d < NFEAT; d++) {
            unsigned long long f2;
            BCAST2(f2, feats[sub][n][d]);
            FMA2(acc, f2, w2v[d]);
        }
        float h0, h1; UNPACK2(h0, h1, acc);
        vmax0 = fmaxf(vmax0, h0);
        vmax1 = fmaxf(vmax1, h1);
    }

    int b = coors[m*4+0], yy = coors[m*4+2], xx = coors[m*4+3];
    size_t px = (((size_t)b*GH + yy)*GW + xx)*CF;
    g_canvas_h[px + f]  = __float2half_rn(vmax0);
    g_canvas_h[px + f1] = __float2half_rn(vmax1);
}

// ================= mma.sync GEMM (multistage, 1 sync/iter) =================
// MODE 0: conv1 implicit GEMM — A gathered from fp16 canvas (zero-fill halo),
//         epilogue relu(+bias) -> g_A2 fp16.
// MODE 1: conv2 — A = g_A2, epilogue +bias -> outp fp32 + rowsum atomics.
template<int BM, int BN, int K, int MODE, int STAGES>
__global__ __launch_bounds__(256) void gemm_mma(const float* __restrict__ bias,
                                                float* __restrict__ outp)
{
    extern __shared__ __align__(1024) char smem[];
    constexpr int NKB = K / 64;
    constexpr int ASZ = BM*128;
    constexpr int BSZ = BN*128;
    constexpr int SSZ = ASZ + BSZ;
    constexpr int MW = 2;
    constexpr int WMS = BM/MW;               // 32
    constexpr int MI  = WMS/16;              // 2
    constexpr int WNS = BN/4;
    constexpr int NJ  = WNS/8;               // 2 (BN=64) / 4 (BN=128)
    constexpr int AIT = BM*8/256;            // 2

    const uint32_t sbase = smem_to_u32(smem);
    const int tid  = threadIdx.x;
    const int lane = tid & 31, wid = tid >> 5;
    const int warpM = wid & (MW-1), warpN = wid >> 1;
    const int bn = blockIdx.x * BN, bm = blockIdx.y * BM;
    const int wm = warpM*WMS, wn = warpN*WNS;

    const __half* __restrict__ Bm = (MODE == 0) ? g_B1 : g_B2;

    // hoisted per-thread A-loader state
    uint32_t dstA[AIT];
    int aoff[AIT];
    int ihb[AIT], iwb[AIT];
    bool mok[AIT];
    #pragma unroll
    for (int i = 0; i < AIT; i++) {
        int c = tid + i*256;
        int r = c >> 3, u = c & 7;
        int m = bm + r;
        dstA[i] = SWZ(r*128 + u*16);
        mok[i] = m < M1;
        if (MODE == 0) {
            int mc = mok[i] ? m : 0;
            int b = mc / 100, p = mc - b*100;
            int hp = p / 10, wp = p - hp*10;
            ihb[i] = 4*hp - 1; iwb[i] = 4*wp - 1;
            aoff[i] = b*(GH*GW*CF) + u*8;
        } else {
            aoff[i] = (mok[i] ? m : 0)*K + u*8;
        }
    }

    // hoisted B-loader state
    constexpr int BIT = BN*8/256;
    uint32_t dstB[BIT];
    int boff[BIT];
    #pragma unroll
    for (int i = 0; i < BIT; i++) {
        int c = tid + i*256;
        int r = c >> 3, u = c & 7;
        dstB[i] = ASZ + SWZ(r*128 + u*16);
        boff[i] = (bn + r)*K + u*8;
    }

    float d[MI][NJ][4];
    #pragma unroll
    for (int mi=0;mi<MI;mi++)
        #pragma unroll
        for (int nj=0;nj<NJ;nj++)
            #pragma unroll
            for (int c=0;c<4;c++) d[mi][nj][c] = 0.f;

    auto load_tile = [&](int kb, int slot) {
        const uint32_t base = sbase + (uint32_t)slot*SSZ;
        int koff = kb*64;
        if (MODE == 0) {
            int tap = kb >> 2, ci0 = (kb & 3) << 6;
            int kh = tap / 3, kw = tap - 3*kh;
            #pragma unroll
            for (int i = 0; i < AIT; i++) {
                int ih = ihb[i] + kh, iw = iwb[i] + kw;
                bool ok = mok[i] && (unsigned)ih < (unsigned)GH && (unsigned)iw < (unsigned)GW;
                const __half* src = g_canvas_h +
                    (ok ? (aoff[i] + (ih*GW + iw)*CF + ci0) : 0);
                cpa16p(base + dstA[i], src, ok ? 16u : 0u);
            }
        } else {
            #pragma unroll
            for (int i = 0; i < AIT; i++)
                cpa16(base + dstA[i], g_A2 + (size_t)aoff[i] + koff);
        }
        #pragma unroll
        for (int i = 0; i < BIT; i++)
            cpa16(base + dstB[i], Bm + (size_t)boff[i] + koff);
    };

    // prefill STAGES-1 tiles
    #pragma unroll
    for (int s = 0; s < STAGES-1; s++) { load_tile(s, s); CP_COMMIT(); }

    for (int kb = 0; kb < NKB; kb++) {
        asm volatile("cp.async.wait_group %0;" :: "n"(STAGES-2) : "memory");
        __syncthreads();

        // issue next tile into the slot everyone just finished reading
        int nk = kb + STAGES-1;
        if (nk < NKB) load_tile(nk, nk % STAGES);
        CP_COMMIT();

        const uint32_t base = sbase + (uint32_t)(kb % STAGES)*SSZ;
        const uint32_t ab = base, bb = base + ASZ;
        #pragma unroll
        for (int kc = 0; kc < 4; kc++) {
            uint32_t afr[MI][4];
            #pragma unroll
            for (int mi = 0; mi < MI; mi++) {
                int row  = wm + mi*16 + (lane & 15);
                int unit = kc*2 + (lane >> 4);
                ldsm4(afr[mi], ab + SWZ(row*128 + unit*16));
            }
            uint32_t bfr[NJ][2];
            #pragma unroll
            for (int p = 0; p < NJ/2; p++) {
                int row  = wn + p*16 + (lane & 7) + ((lane & 16) ? 8 : 0);
                int unit = kc*2 + ((lane >> 3) & 1);
                uint32_t t[4];
                ldsm4(t, bb + SWZ(row*128 + unit*16));
                bfr[p*2][0]   = t[0]; bfr[p*2][1]   = t[1];
                bfr[p*2+1][0] = t[2]; bfr[p*2+1][1] = t[3];
            }
            #pragma unroll
            for (int mi = 0; mi < MI; mi++)
                #pragma unroll
                for (int nj = 0; nj < NJ; nj++)
                    mma16816(d[mi][nj], afr[mi], bfr[nj]);
        }
    }

    // ---------------- epilogue ----------------
    #pragma unroll
    for (int mi = 0; mi < MI; mi++) {
        int m0 = bm + wm + mi*16 + (lane >> 2);
        #pragma unroll
        for (int h = 0; h < 2; h++) {
            int m = m0 + h*8;
            bool ok = m < M1;
            float rsum = 0.f;
            #pragma unroll
            for (int nj = 0; nj < NJ; nj++) {
                int n0 = bn + wn + nj*8 + (lane & 3)*2;
                float v0 = d[mi][nj][h*2+0] + __ldg(bias + n0);
                float v1 = d[mi][nj][h*2+1] + __ldg(bias + n0 + 1);
                if (MODE == 0) {
                    if (ok) {
                        __half hh[2];
                        hh[0] = __float2half_rn(fmaxf(v0, 0.f));
                        hh[1] = __float2half_rn(fmaxf(v1, 0.f));
                        *(uint32_t*)(g_A2 + (size_t)m*K2 + n0) = *(uint32_t*)hh;
                    }
                } else {
                    rsum += v0 + v1;
                    if (ok) {
                        float2 o; o.x = v0; o.y = v1;
                        *(float2*)(outp + (size_t)m*N2 + n0) = o;
                    }
                }
            }
            if (MODE == 1) {
                rsum += __shfl_xor_sync(0xffffffffu, rsum, 1);
                rsum += __shfl_xor_sync(0xffffffffu, rsum, 2);
                if ((lane & 3) == 0 && ok)
                    atomicAdd(&g_rowsum[m], rsum);
            }
        }
    }
}

// ================= epilogues =================
__global__ __launch_bounds__(256) void fixup_kernel(float* __restrict__ out) {
    int m = blockIdx.x;
    bool ok = (g_rowsum[m] != 0.0f);
    if (!ok) {
        float* row = out + (size_t)m * N2;
        for (int i = threadIdx.x; i < N2; i += 256) row[i] = 0.0f;
    }
    if (threadIdx.x == 0) g_valid[m] = ok ? 1 : 0;
}

__global__ void finalize_kernel(float* __restrict__ tail) {
    int t = threadIdx.x, b = t >> 5, lane = t & 31;
    int cnt = 0;
    for (int i = lane; i < 100; i += 32) cnt += g_valid[b*100 + i];
    #pragma unroll
    for (int o = 16; o; o >>= 1) cnt += __shfl_xor_sync(0xffffffffu, cnt, o);
    if (lane == 0) tail[b] = (float)(cnt + 1);
}

// ================= launch =================
extern "C" void kernel_launch(void* const* d_in, const int* in_sizes, int n_in,
                              void* d_out, int out_size) {
    const float* voxels     = (const float*)d_in[0];
    const int*   num_points = (const int*)  d_in[1];
    const int*   coors      = (const int*)  d_in[2];
    const float* w_pfn      = (const float*)d_in[3];
    const float* bn_gamma   = (const float*)d_in[4];
    const float* bn_beta    = (const float*)d_in[5];
    const float* bn_mean    = (const float*)d_in[6];
    const float* bn_var     = (const float*)d_in[7];
    const float* conv1_w    = (const float*)d_in[8];
    const float* conv1_b    = (const float*)d_in[9];
    const float* conv2_w    = (const float*)d_in[10];
    const float* conv2_b    = (const float*)d_in[11];
    float* out = (float*)d_out;

    constexpr int SMEM1 = (64*128 + 64*128)  * 3;    // 49152  (3 stages)
    constexpr int SMEM2 = (64*128 + 128*128) * 4;    // 98304  (4 stages)
    static bool attr_done = false;
    if (!attr_done) {
        cudaFuncSetAttribute(gemm_mma<64, 64,  K1, 0, 3>, cudaFuncAttributeMaxDynamicSharedMemorySize, SMEM1);
        cudaFuncSetAttribute(gemm_mma<64, 128, K2, 1, 4>, cudaFuncAttributeMaxDynamicSharedMemorySize, SMEM2);
        attr_done = true;
    }

    prep_w<<<N1 + N2*K2/4/256, 256>>>(conv1_w, conv2_w);   // 1024 + 4096 blocks

    pfn_kernel<<<MPIL/2, 256>>>(voxels, num_points, coors, w_pfn,
                                bn_gamma, bn_beta, bn_mean, bn_var);

    gemm_mma<64, 64,  K1, 0, 3><<<dim3(N1/64,  MPAD/64), 256, SMEM1>>>(conv1_b, nullptr);
    gemm_mma<64, 128, K2, 1, 4><<<dim3(N2/128, MPAD/64), 256, SMEM2>>>(conv2_b, out);

    fixup_kernel<<<M1, 256>>>(out);
    if (out_size >= OUT_MAIN + BATCH)
        finalize_kernel<<<1, 256>>>(out + OUT_MAIN);
}